// round 7
// baseline (speedup 1.0000x reference)
#include <cuda_runtime.h>
#include <cuda_fp16.h>
#include <cstdint>

#define DMODEL 512
#define DFF 2048
#define NEXP 8
#define TOPK 2
#define NMAX 32768
#define CAPMAX 10240
#define EROWS (NEXP * CAPMAX)

typedef unsigned long long ull;

// ---------------- scratch ----------------
__device__ __align__(1024) __half g_A1h[(size_t)EROWS * DMODEL];
__device__ __align__(1024) __half g_Hh [(size_t)EROWS * DFF];
__device__ __align__(1024) __half g_W1h[(size_t)NEXP * DFF * DMODEL];   // [e][n][k]
__device__ __align__(1024) __half g_W2h[(size_t)NEXP * DMODEL * DFF];   // [e][n][k]
__device__ __align__(1024) float g_EO[(size_t)EROWS * DMODEL];
__device__ int    g_rowidx[EROWS];
__device__ int    g_slot[NMAX * TOPK];
__device__ float  g_wk  [NMAX * TOPK];
__device__ int2   g_ti[NMAX];
__device__ float2 g_tw[NMAX];
__device__ int    g_cnt[NEXP];

// ---------------- helpers ----------------
__device__ __forceinline__ uint32_t s2u(const void* p) {
    uint32_t a;
    asm("{ .reg .u64 t; cvta.to.shared.u64 t, %1; cvt.u32.u64 %0, t; }" : "=r"(a) : "l"(p));
    return a;
}
__device__ __forceinline__ float gelu_exact(float v) {
    return 0.5f * v * (1.0f + erff(v * 0.7071067811865476f));
}
__device__ __forceinline__ uint32_t pack_h2(__half a, __half b) {
    return (uint32_t)__half_as_ushort(a) | ((uint32_t)__half_as_ushort(b) << 16);
}

__device__ __forceinline__ void cp16(uint32_t s, const void* g) {
    asm volatile("cp.async.cg.shared.global [%0], [%1], 16;" :: "r"(s), "l"(g));
}
__device__ __forceinline__ void cp_commit() { asm volatile("cp.async.commit_group;"); }
template<int N> __device__ __forceinline__ void cp_wait() {
    asm volatile("cp.async.wait_group %0;" :: "n"(N));
}
__device__ __forceinline__ void ldm_x4(uint32_t* r, uint32_t a) {
    asm volatile("ldmatrix.sync.aligned.m8n8.x4.shared.b16 {%0,%1,%2,%3}, [%4];"
                 : "=r"(r[0]), "=r"(r[1]), "=r"(r[2]), "=r"(r[3]) : "r"(a));
}
__device__ __forceinline__ void mma16816(float* c, const uint32_t* a, const uint32_t* b) {
    asm volatile(
        "mma.sync.aligned.m16n8k16.row.col.f32.f16.f16.f32 "
        "{%0,%1,%2,%3}, {%4,%5,%6,%7}, {%8,%9}, {%0,%1,%2,%3};"
        : "+f"(c[0]), "+f"(c[1]), "+f"(c[2]), "+f"(c[3])
        : "r"(a[0]), "r"(a[1]), "r"(a[2]), "r"(a[3]), "r"(b[0]), "r"(b[1]));
}

// ---------------- router ----------------
__global__ void router_kernel(const float* __restrict__ x,
                              const float* __restrict__ Wr,
                              const float* __restrict__ br, int N) {
    int warp = (blockIdx.x * blockDim.x + threadIdx.x) >> 5;
    int lane = threadIdx.x & 31;
    if (warp >= N) return;
    const float* xr = x + (size_t)warp * DMODEL;
    float acc[8] = {0, 0, 0, 0, 0, 0, 0, 0};
    for (int d = lane; d < DMODEL; d += 32) {
        float xv = xr[d];
        float4 w0 = *(const float4*)(Wr + (size_t)d * 8);
        float4 w1 = *(const float4*)(Wr + (size_t)d * 8 + 4);
        acc[0] += xv * w0.x; acc[1] += xv * w0.y;
        acc[2] += xv * w0.z; acc[3] += xv * w0.w;
        acc[4] += xv * w1.x; acc[5] += xv * w1.y;
        acc[6] += xv * w1.z; acc[7] += xv * w1.w;
    }
    #pragma unroll
    for (int o = 16; o; o >>= 1)
        #pragma unroll
        for (int e = 0; e < 8; e++)
            acc[e] += __shfl_xor_sync(0xFFFFFFFFu, acc[e], o);
    if (lane == 0) {
        float l[8], p[8];
        float m = -1e30f;
        #pragma unroll
        for (int e = 0; e < 8; e++) { l[e] = acc[e] + br[e]; m = fmaxf(m, l[e]); }
        float s = 0.f;
        #pragma unroll
        for (int e = 0; e < 8; e++) { p[e] = expf(l[e] - m); s += p[e]; }
        float inv = 1.0f / s;
        #pragma unroll
        for (int e = 0; e < 8; e++) p[e] *= inv;
        int i1 = 0; float p1 = p[0];
        #pragma unroll
        for (int e = 1; e < 8; e++) if (p[e] > p1) { p1 = p[e]; i1 = e; }
        int i2 = -1; float p2 = -1.0f;
        #pragma unroll
        for (int e = 0; e < 8; e++) if (e != i1 && p[e] > p2) { p2 = p[e]; i2 = e; }
        float den = p1 + p2 + 1e-9f;
        g_ti[warp] = make_int2(i1, i2);
        g_tw[warp] = make_float2(p1 / den, p2 / den);
    }
}

// ---------------- dispatch ----------------
__global__ void dispatch_kernel(int N, int cap) {
    const int T = 1024;
    int t = threadIdx.x;
    int slots = N * TOPK;
    int C = (slots + T - 1) / T;
    __shared__ int sc[8][1024];
    __shared__ int stot[8];
    int cnt[8] = {0, 0, 0, 0, 0, 0, 0, 0};
    int s0 = t * C, s1 = min(s0 + C, slots);
    for (int s = s0; s < s1; s++) {
        int2 ti = g_ti[s >> 1];
        cnt[(s & 1) ? ti.y : ti.x]++;
    }
    #pragma unroll
    for (int e = 0; e < 8; e++) sc[e][t] = cnt[e];
    __syncthreads();
    if (t < 8) {
        int run = 0;
        for (int i = 0; i < T; i++) { int v = sc[t][i]; sc[t][i] = run; run += v; }
        stot[t] = run;
        g_cnt[t] = min(run, cap);
    }
    __syncthreads();
    int pos[8];
    #pragma unroll
    for (int e = 0; e < 8; e++) pos[e] = sc[e][t];
    for (int s = s0; s < s1; s++) {
        int tok = s >> 1, k = s & 1;
        int2 ti = g_ti[tok];
        float2 tw = g_tw[tok];
        int e = k ? ti.y : ti.x;
        float w = k ? tw.y : tw.x;
        int p = pos[e]++;
        bool keep = p < cap;
        int slot = e * cap + p;
        if (keep) g_rowidx[slot] = tok;
        g_slot[s] = keep ? slot : 0;
        g_wk[s]   = keep ? w : 0.0f;
    }
    for (int e = 0; e < 8; e++) {
        int c = min(stot[e], cap);
        for (int p = c + t; p < cap; p += T) g_rowidx[e * cap + p] = -1;
    }
}

// ---------------- weight convert+transpose: [e][R][C] f32 -> [e][C][R] fp16 ----------------
__global__ void wconvert_kernel(const float* __restrict__ src,
                                __half* __restrict__ dh, int R, int C) {
    int e = blockIdx.z;
    int c0 = blockIdx.x * 32, r0 = blockIdx.y * 32;
    __shared__ float t[32][33];
    int tx = threadIdx.x & 31, ty = threadIdx.x >> 5;
    const float* s = src + (size_t)e * R * C;
    #pragma unroll
    for (int i = 0; i < 4; i++)
        t[ty + i * 8][tx] = s[(size_t)(r0 + ty + i * 8) * C + c0 + tx];
    __syncthreads();
    size_t ob = (size_t)e * C * R;
    #pragma unroll
    for (int i = 0; i < 4; i++) {
        int c = c0 + ty + i * 8;
        float v = t[tx][ty + i * 8];
        dh[ob + (size_t)c * R + r0 + tx] = __float2half_rn(v);
    }
}

// ---------------- gather: tokens -> fp16 plane ----------------
__global__ void gather_kernel(const float* __restrict__ x, __half* __restrict__ Ah) {
    int gid = blockIdx.x * 256 + threadIdx.x;
    int row = gid >> 7, j = gid & 127;
    int tok = g_rowidx[row];
    float4 v = make_float4(0, 0, 0, 0);
    if (tok >= 0) v = ((const float4*)(x + (size_t)tok * DMODEL))[j];
    uint2 ph = make_uint2(pack_h2(__float2half_rn(v.x), __float2half_rn(v.y)),
                          pack_h2(__float2half_rn(v.z), __float2half_rn(v.w)));
    ((uint2*)(Ah + (size_t)row * DMODEL))[j] = ph;
}

// ---------------- fp16 mma.sync GEMM: tile 128x256, K-stage 32, 5-stage cp.async ----------------
#define RSTR 80
#define A_PL (128 * RSTR)          // 10240
#define B_PL (256 * RSTR)          // 20480
#define ST_A  0
#define ST_B  (A_PL)
#define ST_SZ (A_PL + B_PL)        // 30720
#define NST 5
#define SMEM_TOT (NST * ST_SZ)     // 153600
// epilogue staging strides (bytes): chosen for conflict-free/low-conflict STS
#define G1_RS 528                  // 128 rows x (512B data + 16 pad) = 67584  <= SMEM_TOT
#define G2_RS 1040                 // 128 rows x (1024B data + 16 pad) = 133120 <= SMEM_TOT

template<int KTOT, int NF, bool G1>
__global__ void __launch_bounds__(256, 1)
gemm_mma(const __half* __restrict__ Ah, const __half* __restrict__ Bh,
         const float* __restrict__ bias,
         __half* __restrict__ Oh, float* __restrict__ Of, int cap, int tpe) {
    int e = blockIdx.y / tpe, mt = blockIdx.y % tpe;
    if (mt * 128 >= g_cnt[e]) return;
    const int row0 = mt * 128;
    const int n0 = blockIdx.x * 256;
    extern __shared__ char sm[];
    const uint32_t sb = s2u(sm);
    const int tid = threadIdx.x;
    const int wid = tid >> 5, lane = tid & 31;
    const int wm = wid >> 2, wn = wid & 3;

    const size_t arow0 = (size_t)e * cap + row0;
    const __half* pA = Ah + arow0 * KTOT;
    const __half* pB = Bh + ((size_t)e * NF + n0) * KTOT;

    auto load_stage = [&](int buf, int kbase) {
        uint32_t sbase = sb + buf * ST_SZ;
        #pragma unroll
        for (int j = 0; j < 2; j++) {               // A: 512 16B-chunks
            int idx = j * 256 + tid;
            int r = idx >> 2, c = idx & 3;
            cp16(sbase + ST_A + r * RSTR + c * 16, pA + (size_t)r * KTOT + kbase + c * 8);
        }
        #pragma unroll
        for (int j = 0; j < 4; j++) {               // B: 1024 16B-chunks
            int idx = j * 256 + tid;
            int r = idx >> 2, c = idx & 3;
            cp16(sbase + ST_B + r * RSTR + c * 16, pB + (size_t)r * KTOT + kbase + c * 8);
        }
    };

    float acc[4][8][4];
    #pragma unroll
    for (int i = 0; i < 4; i++)
        #pragma unroll
        for (int j = 0; j < 8; j++)
            #pragma unroll
            for (int q = 0; q < 4; q++) acc[i][j][q] = 0.f;

    const uint32_t aAddr = (uint32_t)(wm * 64 + (lane & 15)) * RSTR + (lane >> 4) * 16;
    const uint32_t bAddr = (uint32_t)(wn * 64 + ((lane >> 4) & 1) * 8 + (lane & 7)) * RSTR
                           + ((lane >> 3) & 1) * 16;

    const int NK = KTOT / 32;
    load_stage(0, 0);  cp_commit();
    load_stage(1, 32); cp_commit();
    load_stage(2, 64); cp_commit();
    load_stage(3, 96); cp_commit();

    for (int s = 0; s < NK; s++) {
        cp_wait<3>();
        __syncthreads();

        uint32_t sbase = sb + (s % NST) * ST_SZ;
        #pragma unroll
        for (int kk = 0; kk < 2; kk++) {
            uint32_t koff = kk * 32;
            uint32_t ah[4][4], bh[4][4];
            #pragma unroll
            for (int mi = 0; mi < 4; mi++)
                ldm_x4(ah[mi], sbase + ST_A + aAddr + mi * (16 * RSTR) + koff);
            #pragma unroll
            for (int nq = 0; nq < 4; nq++)
                ldm_x4(bh[nq], sbase + ST_B + bAddr + nq * (16 * RSTR) + koff);
            #pragma unroll
            for (int mi = 0; mi < 4; mi++)
                #pragma unroll
                for (int nq = 0; nq < 4; nq++) {
                    mma16816(acc[mi][2 * nq],     ah[mi], bh[nq]);
                    mma16816(acc[mi][2 * nq + 1], ah[mi], bh[nq] + 2);
                }
        }

        if (s + 4 < NK) load_stage((s + 4) % NST, (s + 4) * 32);
        cp_commit();
    }

    // ---------------- epilogue: stage in smem, then coalesced stores ----------------
    const int colloc = wn * 64 + (lane & 3) * 2;    // col within 256-wide tile
    const int rowloc = wm * 64 + (lane >> 2);       // row within 128-tall tile
    float2 bvv[8];
    #pragma unroll
    for (int ni = 0; ni < 8; ni++)
        bvv[ni] = *(const float2*)(bias + (size_t)e * NF + n0 + colloc + ni * 8);

    cp_wait<0>();
    __syncthreads();   // all mainloop smem reads done; safe to overwrite pipeline smem

    if (G1) {
        // fp16 staging: row stride G1_RS bytes
        #pragma unroll
        for (int mi = 0; mi < 4; mi++)
            #pragma unroll
            for (int half = 0; half < 2; half++) {
                int r = rowloc + mi * 16 + half * 8;
                #pragma unroll
                for (int ni = 0; ni < 8; ni++) {
                    int col = colloc + ni * 8;
                    float g0 = gelu_exact(acc[mi][ni][half * 2 + 0] + bvv[ni].x);
                    float g1 = gelu_exact(acc[mi][ni][half * 2 + 1] + bvv[ni].y);
                    *(uint32_t*)(sm + r * G1_RS + col * 2) =
                        pack_h2(__float2half_rn(g0), __float2half_rn(g1));
                }
            }
        __syncthreads();
        // copy out: 128 rows x 512B, 16B chunks, fully coalesced
        #pragma unroll
        for (int i = 0; i < 16; i++) {
            int idx = i * 256 + tid;            // 4096 chunks
            int row = idx >> 5, ch = idx & 31;
            uint4 v = *(const uint4*)(sm + row * G1_RS + ch * 16);
            *(uint4*)(Oh + (arow0 + row) * NF + n0 + ch * 8) = v;
        }
    } else {
        // f32 staging: row stride G2_RS bytes
        #pragma unroll
        for (int mi = 0; mi < 4; mi++)
            #pragma unroll
            for (int half = 0; half < 2; half++) {
                int r = rowloc + mi * 16 + half * 8;
                #pragma unroll
                for (int ni = 0; ni < 8; ni++) {
                    int col = colloc + ni * 8;
                    float v0 = acc[mi][ni][half * 2 + 0] + bvv[ni].x;
                    float v1 = acc[mi][ni][half * 2 + 1] + bvv[ni].y;
                    *(float2*)(sm + r * G2_RS + col * 4) = make_float2(v0, v1);
                }
            }
        __syncthreads();
        // copy out: 128 rows x 1024B, 16B chunks
        #pragma unroll
        for (int i = 0; i < 32; i++) {
            int idx = i * 256 + tid;            // 8192 chunks
            int row = idx >> 6, ch = idx & 63;
            uint4 v = *(const uint4*)(sm + row * G2_RS + ch * 16);
            *(uint4*)(Of + (arow0 + row) * NF + n0 + ch * 4) = v;
        }
    }
}

// ---------------- combine ----------------
__global__ void combine_kernel(float* __restrict__ out, int N) {
    int gid = blockIdx.x * blockDim.x + threadIdx.x;
    if (gid >= N * (DMODEL / 4)) return;
    int tok = gid >> 7;
    int j = gid & 127;
    int s0 = g_slot[2 * tok], s1 = g_slot[2 * tok + 1];
    float w0 = g_wk[2 * tok], w1 = g_wk[2 * tok + 1];
    float inv = 1.0f / (w0 + w1 + 1e-9f);
    w0 *= inv; w1 *= inv;
    const float4* e0 = (const float4*)(g_EO + (size_t)s0 * DMODEL);
    const float4* e1 = (const float4*)(g_EO + (size_t)s1 * DMODEL);
    float4 a = e0[j], b = e1[j];
    float4 r;
    r.x = w0 * a.x + w1 * b.x;
    r.y = w0 * a.y + w1 * b.y;
    r.z = w0 * a.z + w1 * b.z;
    r.w = w0 * a.w + w1 * b.w;
    ((float4*)out)[gid] = r;
}

// ---------------- launch ----------------
extern "C" void kernel_launch(void* const* d_in, const int* in_sizes, int n_in,
                              void* d_out, int out_size) {
    const float* x  = (const float*)d_in[0];
    const float* Wr = (const float*)d_in[1];
    const float* br = (const float*)d_in[2];
    const float* W1 = (const float*)d_in[3];
    const float* b1 = (const float*)d_in[4];
    const float* W2 = (const float*)d_in[5];
    const float* b2 = (const float*)d_in[6];
    float* out = (float*)d_out;

    int N = in_sizes[0] / DMODEL;
    if (N > NMAX) N = NMAX;
    int cap = (5 * N + 15) / 16;
    if (cap > CAPMAX) cap = CAPMAX;
    int tpe = (cap + 127) / 128;

    void *a1h, *hh, *w1h, *w2h, *eo;
    cudaGetSymbolAddress(&a1h, g_A1h);
    cudaGetSymbolAddress(&hh,  g_Hh);
    cudaGetSymbolAddress(&w1h, g_W1h); cudaGetSymbolAddress(&w2h, g_W2h);
    cudaGetSymbolAddress(&eo,  g_EO);

    cudaFuncSetAttribute(gemm_mma<DMODEL, DFF, true>,
                         cudaFuncAttributeMaxDynamicSharedMemorySize, SMEM_TOT);
    cudaFuncSetAttribute(gemm_mma<DFF, DMODEL, false>,
                         cudaFuncAttributeMaxDynamicSharedMemorySize, SMEM_TOT);

    router_kernel<<<(N * 32 + 255) / 256, 256>>>(x, Wr, br, N);
    dispatch_kernel<<<1, 1024>>>(N, cap);
    wconvert_kernel<<<dim3(DFF / 32, DMODEL / 32, NEXP), 256>>>(
        W1, (__half*)w1h, DMODEL, DFF);
    wconvert_kernel<<<dim3(DMODEL / 32, DFF / 32, NEXP), 256>>>(
        W2, (__half*)w2h, DFF, DMODEL);
    gather_kernel<<<(NEXP * cap * 128) / 256, 256>>>(x, (__half*)a1h);

    dim3 g1(DFF / 256, NEXP * tpe);
    gemm_mma<DMODEL, DFF, true><<<g1, 256, SMEM_TOT>>>(
        (const __half*)a1h, (const __half*)w1h, b1,
        (__half*)hh, nullptr, cap, tpe);

    dim3 g2(DMODEL / 256, NEXP * tpe);
    gemm_mma<DFF, DMODEL, false><<<g2, 256, SMEM_TOT>>>(
        (const __half*)hh, (const __half*)w2h, b2,
        nullptr, (float*)eo, cap, tpe);

    combine_kernel<<<(N * (DMODEL / 4) + 255) / 256, 256>>>(out, N);
}

// round 9
// speedup vs baseline: 1.1105x; 1.1105x over previous
#include <cuda_runtime.h>
#include <cuda_fp16.h>
#include <cstdint>

#define DMODEL 512
#define DFF 2048
#define NEXP 8
#define TOPK 2
#define NMAX 32768
#define CAPMAX 10240
#define EROWS (NEXP * CAPMAX)

typedef unsigned long long ull;

// ---------------- scratch ----------------
__device__ __align__(1024) __half g_A1h[(size_t)EROWS * DMODEL];
__device__ __align__(1024) __half g_Hh [(size_t)EROWS * DFF];
__device__ __align__(1024) __half g_W1h[(size_t)NEXP * DFF * DMODEL];   // [e][n][k]
__device__ __align__(1024) __half g_W2h[(size_t)NEXP * DMODEL * DFF];   // [e][n][k]
__device__ int    g_rowidx[EROWS];     // slot -> token (-1 pad)
__device__ float  g_wn[EROWS];         // slot -> normalized combine weight
__device__ int2   g_ti[NMAX];
__device__ float2 g_tw[NMAX];
__device__ int    g_cnt[NEXP];

// ---------------- helpers ----------------
__device__ __forceinline__ uint32_t s2u(const void* p) {
    uint32_t a;
    asm("{ .reg .u64 t; cvta.to.shared.u64 t, %1; cvt.u32.u64 %0, t; }" : "=r"(a) : "l"(p));
    return a;
}
__device__ __forceinline__ float gelu_exact(float v) {
    return 0.5f * v * (1.0f + erff(v * 0.7071067811865476f));
}
__device__ __forceinline__ uint32_t pack_h2(__half a, __half b) {
    return (uint32_t)__half_as_ushort(a) | ((uint32_t)__half_as_ushort(b) << 16);
}

__device__ __forceinline__ void cp16(uint32_t s, const void* g) {
    asm volatile("cp.async.cg.shared.global [%0], [%1], 16;" :: "r"(s), "l"(g));
}
__device__ __forceinline__ void cp_commit() { asm volatile("cp.async.commit_group;"); }
template<int N> __device__ __forceinline__ void cp_wait() {
    asm volatile("cp.async.wait_group %0;" :: "n"(N));
}
__device__ __forceinline__ void ldm_x4(uint32_t* r, uint32_t a) {
    asm volatile("ldmatrix.sync.aligned.m8n8.x4.shared.b16 {%0,%1,%2,%3}, [%4];"
                 : "=r"(r[0]), "=r"(r[1]), "=r"(r[2]), "=r"(r[3]) : "r"(a));
}
__device__ __forceinline__ void mma16816(float* c, const uint32_t* a, const uint32_t* b) {
    asm volatile(
        "mma.sync.aligned.m16n8k16.row.col.f32.f16.f16.f32 "
        "{%0,%1,%2,%3}, {%4,%5,%6,%7}, {%8,%9}, {%0,%1,%2,%3};"
        : "+f"(c[0]), "+f"(c[1]), "+f"(c[2]), "+f"(c[3])
        : "r"(a[0]), "r"(a[1]), "r"(a[2]), "r"(a[3]), "r"(b[0]), "r"(b[1]));
}

// ---------------- router ----------------
__global__ void router_kernel(const float* __restrict__ x,
                              const float* __restrict__ Wr,
                              const float* __restrict__ br, int N) {
    int warp = (blockIdx.x * blockDim.x + threadIdx.x) >> 5;
    int lane = threadIdx.x & 31;
    if (warp >= N) return;
    const float* xr = x + (size_t)warp * DMODEL;
    float acc[8] = {0, 0, 0, 0, 0, 0, 0, 0};
    for (int d = lane; d < DMODEL; d += 32) {
        float xv = xr[d];
        float4 w0 = *(const float4*)(Wr + (size_t)d * 8);
        float4 w1 = *(const float4*)(Wr + (size_t)d * 8 + 4);
        acc[0] += xv * w0.x; acc[1] += xv * w0.y;
        acc[2] += xv * w0.z; acc[3] += xv * w0.w;
        acc[4] += xv * w1.x; acc[5] += xv * w1.y;
        acc[6] += xv * w1.z; acc[7] += xv * w1.w;
    }
    #pragma unroll
    for (int o = 16; o; o >>= 1)
        #pragma unroll
        for (int e = 0; e < 8; e++)
            acc[e] += __shfl_xor_sync(0xFFFFFFFFu, acc[e], o);
    if (lane == 0) {
        float l[8], p[8];
        float m = -1e30f;
        #pragma unroll
        for (int e = 0; e < 8; e++) { l[e] = acc[e] + br[e]; m = fmaxf(m, l[e]); }
        float s = 0.f;
        #pragma unroll
        for (int e = 0; e < 8; e++) { p[e] = expf(l[e] - m); s += p[e]; }
        float inv = 1.0f / s;
        #pragma unroll
        for (int e = 0; e < 8; e++) p[e] *= inv;
        int i1 = 0; float p1 = p[0];
        #pragma unroll
        for (int e = 1; e < 8; e++) if (p[e] > p1) { p1 = p[e]; i1 = e; }
        int i2 = -1; float p2 = -1.0f;
        #pragma unroll
        for (int e = 0; e < 8; e++) if (e != i1 && p[e] > p2) { p2 = p[e]; i2 = e; }
        float den = p1 + p2 + 1e-9f;
        g_ti[warp] = make_int2(i1, i2);
        g_tw[warp] = make_float2(p1 / den, p2 / den);
    }
}

// ---------------- dispatch (ordered scan; writes per-slot normalized weights) ----------------
__global__ void dispatch_kernel(int N, int cap) {
    const int T = 1024;
    int t = threadIdx.x;
    int slots = N * TOPK;
    int C = (slots + T - 1) / T;      // 64 for N=32768 (even: token pairs stay together)
    __shared__ int sc[8][1024];
    __shared__ int stot[8];
    int cnt[8] = {0, 0, 0, 0, 0, 0, 0, 0};
    int s0 = t * C, s1 = min(s0 + C, slots);
    for (int s = s0; s < s1; s++) {
        int2 ti = g_ti[s >> 1];
        cnt[(s & 1) ? ti.y : ti.x]++;
    }
    #pragma unroll
    for (int e = 0; e < 8; e++) sc[e][t] = cnt[e];
    __syncthreads();
    if (t < 8) {
        int run = 0;
        for (int i = 0; i < T; i++) { int v = sc[t][i]; sc[t][i] = run; run += v; }
        stot[t] = run;
        g_cnt[t] = min(run, cap);
    }
    __syncthreads();
    int pos[8];
    #pragma unroll
    for (int e = 0; e < 8; e++) pos[e] = sc[e][t];
    for (int s = s0; s < s1; s += 2) {
        int tok = s >> 1;
        int2 ti = g_ti[tok];
        float2 tw = g_tw[tok];
        int p0 = pos[ti.x]++;
        int p1 = pos[ti.y]++;
        bool k0 = p0 < cap, k1 = p1 < cap;
        float w0 = k0 ? tw.x : 0.0f;
        float w1 = k1 ? tw.y : 0.0f;
        float inv = 1.0f / (w0 + w1 + 1e-9f);
        if (k0) {
            int sl = ti.x * cap + p0;
            g_rowidx[sl] = tok; g_wn[sl] = w0 * inv;
        }
        if (k1) {
            int sl = ti.y * cap + p1;
            g_rowidx[sl] = tok; g_wn[sl] = w1 * inv;
        }
    }
    __syncthreads();
    for (int e = 0; e < 8; e++) {
        int c = min(stot[e], cap);
        for (int p = c + t; p < cap; p += T) g_rowidx[e * cap + p] = -1;
    }
}

// ---------------- weight convert+transpose: [e][R][C] f32 -> [e][C][R] fp16 ----------------
__global__ void wconvert_kernel(const float* __restrict__ src,
                                __half* __restrict__ dh, int R, int C) {
    int e = blockIdx.z;
    int c0 = blockIdx.x * 32, r0 = blockIdx.y * 32;
    __shared__ float t[32][33];
    int tx = threadIdx.x & 31, ty = threadIdx.x >> 5;
    const float* s = src + (size_t)e * R * C;
    #pragma unroll
    for (int i = 0; i < 4; i++)
        t[ty + i * 8][tx] = s[(size_t)(r0 + ty + i * 8) * C + c0 + tx];
    __syncthreads();
    size_t ob = (size_t)e * C * R;
    #pragma unroll
    for (int i = 0; i < 4; i++) {
        int c = c0 + ty + i * 8;
        float v = t[tx][ty + i * 8];
        dh[ob + (size_t)c * R + r0 + tx] = __float2half_rn(v);
    }
}

// ---------------- gather: tokens -> fp16 plane ----------------
__global__ void gather_kernel(const float* __restrict__ x, __half* __restrict__ Ah) {
    int gid = blockIdx.x * 256 + threadIdx.x;
    int row = gid >> 7, j = gid & 127;
    int tok = g_rowidx[row];
    float4 v = make_float4(0, 0, 0, 0);
    if (tok >= 0) v = ((const float4*)(x + (size_t)tok * DMODEL))[j];
    uint2 ph = make_uint2(pack_h2(__float2half_rn(v.x), __float2half_rn(v.y)),
                          pack_h2(__float2half_rn(v.z), __float2half_rn(v.w)));
    ((uint2*)(Ah + (size_t)row * DMODEL))[j] = ph;
}

// ---------------- fp16 mma.sync GEMM: tile 128x256, K-stage 32, 5-stage cp.async ----------------
#define RSTR 80
#define A_PL (128 * RSTR)          // 10240
#define B_PL (256 * RSTR)          // 20480
#define ST_A  0
#define ST_B  (A_PL)
#define ST_SZ (A_PL + B_PL)        // 30720
#define NST 5
#define SMEM_TOT (NST * ST_SZ)     // 153600

template<int KTOT, int NF, bool G1>
__global__ void __launch_bounds__(256, 1)
gemm_mma(const __half* __restrict__ Ah, const __half* __restrict__ Bh,
         const float* __restrict__ bias,
         __half* __restrict__ Oh, float* __restrict__ Of, int cap, int tpe) {
    int e = blockIdx.y / tpe, mt = blockIdx.y % tpe;
    if (mt * 128 >= g_cnt[e]) return;
    const int row0 = mt * 128;
    const int n0 = blockIdx.x * 256;
    extern __shared__ char sm[];
    const uint32_t sb = s2u(sm);
    const int tid = threadIdx.x;
    const int wid = tid >> 5, lane = tid & 31;
    const int wm = wid >> 2, wn = wid & 3;

    const size_t arow0 = (size_t)e * cap + row0;
    const __half* pA = Ah + arow0 * KTOT;
    const __half* pB = Bh + ((size_t)e * NF + n0) * KTOT;

    auto load_stage = [&](int buf, int kbase) {
        uint32_t sbase = sb + buf * ST_SZ;
        #pragma unroll
        for (int j = 0; j < 2; j++) {               // A: 512 16B-chunks
            int idx = j * 256 + tid;
            int r = idx >> 2, c = idx & 3;
            cp16(sbase + ST_A + r * RSTR + c * 16, pA + (size_t)r * KTOT + kbase + c * 8);
        }
        #pragma unroll
        for (int j = 0; j < 4; j++) {               // B: 1024 16B-chunks
            int idx = j * 256 + tid;
            int r = idx >> 2, c = idx & 3;
            cp16(sbase + ST_B + r * RSTR + c * 16, pB + (size_t)r * KTOT + kbase + c * 8);
        }
    };

    float acc[4][8][4];
    #pragma unroll
    for (int i = 0; i < 4; i++)
        #pragma unroll
        for (int j = 0; j < 8; j++)
            #pragma unroll
            for (int q = 0; q < 4; q++) acc[i][j][q] = 0.f;

    const uint32_t aAddr = (uint32_t)(wm * 64 + (lane & 15)) * RSTR + (lane >> 4) * 16;
    const uint32_t bAddr = (uint32_t)(wn * 64 + ((lane >> 4) & 1) * 8 + (lane & 7)) * RSTR
                           + ((lane >> 3) & 1) * 16;

    const int NK = KTOT / 32;
    load_stage(0, 0);  cp_commit();
    load_stage(1, 32); cp_commit();
    load_stage(2, 64); cp_commit();
    load_stage(3, 96); cp_commit();

    for (int s = 0; s < NK; s++) {
        cp_wait<3>();
        __syncthreads();

        uint32_t sbase = sb + (s % NST) * ST_SZ;
        #pragma unroll
        for (int kk = 0; kk < 2; kk++) {
            uint32_t koff = kk * 32;
            uint32_t ah[4][4], bh[4][4];
            #pragma unroll
            for (int mi = 0; mi < 4; mi++)
                ldm_x4(ah[mi], sbase + ST_A + aAddr + mi * (16 * RSTR) + koff);
            #pragma unroll
            for (int nq = 0; nq < 4; nq++)
                ldm_x4(bh[nq], sbase + ST_B + bAddr + nq * (16 * RSTR) + koff);
            #pragma unroll
            for (int mi = 0; mi < 4; mi++)
                #pragma unroll
                for (int nq = 0; nq < 4; nq++) {
                    mma16816(acc[mi][2 * nq],     ah[mi], bh[nq]);
                    mma16816(acc[mi][2 * nq + 1], ah[mi], bh[nq] + 2);
                }
        }

        if (s + 4 < NK) load_stage((s + 4) % NST, (s + 4) * 32);
        cp_commit();
    }

    // ---------------- epilogue (direct stores; G2 fused combine via atomics) ----------------
    const int colbase = n0 + wn * 64 + (lane & 3) * 2;
    const int rowbase = wm * 64 + (lane >> 2);
    float2 bvv[8];
    #pragma unroll
    for (int ni = 0; ni < 8; ni++)
        bvv[ni] = *(const float2*)(bias + (size_t)e * NF + colbase + ni * 8);
    #pragma unroll
    for (int mi = 0; mi < 4; mi++) {
        #pragma unroll
        for (int half = 0; half < 2; half++) {
            int r = rowbase + mi * 16 + half * 8;
            size_t grow = arow0 + r;
            if (G1) {
                #pragma unroll
                for (int ni = 0; ni < 8; ni++) {
                    int col = colbase + ni * 8;
                    float g0 = gelu_exact(acc[mi][ni][half * 2 + 0] + bvv[ni].x);
                    float g1 = gelu_exact(acc[mi][ni][half * 2 + 1] + bvv[ni].y);
                    *(uint32_t*)(Oh + grow * NF + col) =
                        pack_h2(__float2half_rn(g0), __float2half_rn(g1));
                }
            } else {
                int tok = g_rowidx[grow];
                if (tok >= 0) {
                    float w = g_wn[grow];
                    float* op = Of + (size_t)tok * DMODEL;
                    #pragma unroll
                    for (int ni = 0; ni < 8; ni++) {
                        int col = colbase + ni * 8;
                        float v0 = w * (acc[mi][ni][half * 2 + 0] + bvv[ni].x);
                        float v1 = w * (acc[mi][ni][half * 2 + 1] + bvv[ni].y);
                        atomicAdd(op + col,     v0);
                        atomicAdd(op + col + 1, v1);
                    }
                }
            }
        }
    }
}

// ---------------- launch ----------------
extern "C" void kernel_launch(void* const* d_in, const int* in_sizes, int n_in,
                              void* d_out, int out_size) {
    const float* x  = (const float*)d_in[0];
    const float* Wr = (const float*)d_in[1];
    const float* br = (const float*)d_in[2];
    const float* W1 = (const float*)d_in[3];
    const float* b1 = (const float*)d_in[4];
    const float* W2 = (const float*)d_in[5];
    const float* b2 = (const float*)d_in[6];
    float* out = (float*)d_out;

    int N = in_sizes[0] / DMODEL;
    if (N > NMAX) N = NMAX;
    int cap = (5 * N + 15) / 16;
    if (cap > CAPMAX) cap = CAPMAX;
    int tpe = (cap + 127) / 128;

    void *a1h, *hh, *w1h, *w2h;
    cudaGetSymbolAddress(&a1h, g_A1h);
    cudaGetSymbolAddress(&hh,  g_Hh);
    cudaGetSymbolAddress(&w1h, g_W1h); cudaGetSymbolAddress(&w2h, g_W2h);

    cudaFuncSetAttribute(gemm_mma<DMODEL, DFF, true>,
                         cudaFuncAttributeMaxDynamicSharedMemorySize, SMEM_TOT);
    cudaFuncSetAttribute(gemm_mma<DFF, DMODEL, false>,
                         cudaFuncAttributeMaxDynamicSharedMemorySize, SMEM_TOT);

    cudaMemsetAsync(out, 0, (size_t)out_size * sizeof(float));
    router_kernel<<<(N * 32 + 255) / 256, 256>>>(x, Wr, br, N);
    dispatch_kernel<<<1, 1024>>>(N, cap);
    wconvert_kernel<<<dim3(DFF / 32, DMODEL / 32, NEXP), 256>>>(
        W1, (__half*)w1h, DMODEL, DFF);
    wconvert_kernel<<<dim3(DMODEL / 32, DFF / 32, NEXP), 256>>>(
        W2, (__half*)w2h, DFF, DMODEL);
    gather_kernel<<<(NEXP * cap * 128) / 256, 256>>>(x, (__half*)a1h);

    dim3 g1(DFF / 256, NEXP * tpe);
    gemm_mma<DMODEL, DFF, true><<<g1, 256, SMEM_TOT>>>(
        (const __half*)a1h, (const __half*)w1h, b1,
        (__half*)hh, nullptr, cap, tpe);

    dim3 g2(DMODEL / 256, NEXP * tpe);
    gemm_mma<DFF, DMODEL, false><<<g2, 256, SMEM_TOT>>>(
        (const __half*)hh, (const __half*)w2h, b2,
        nullptr, out, cap, tpe);
}

// round 10
// speedup vs baseline: 1.1361x; 1.0230x over previous
#include <cuda_runtime.h>
#include <cuda_fp16.h>
#include <cstdint>

#define DMODEL 512
#define DFF 2048
#define NEXP 8
#define TOPK 2
#define NMAX 32768
#define CAPMAX 10240
#define EROWS (NEXP * CAPMAX)

typedef unsigned long long ull;

// ---------------- scratch ----------------
__device__ __align__(1024) __half g_A1h[(size_t)EROWS * DMODEL];
__device__ __align__(1024) __half g_Hh [(size_t)EROWS * DFF];
__device__ __align__(1024) __half g_W1h[(size_t)NEXP * DFF * DMODEL];   // [e][n][k]
__device__ __align__(1024) __half g_W2h[(size_t)NEXP * DMODEL * DFF];   // [e][n][k]
__device__ int    g_rowidx[EROWS];     // slot -> token (-1 pad)
__device__ float  g_wn[EROWS];         // slot -> normalized combine weight
__device__ int2   g_ti[NMAX];
__device__ float2 g_tw[NMAX];
__device__ int    g_cnt[NEXP];

// ---------------- helpers ----------------
__device__ __forceinline__ uint32_t s2u(const void* p) {
    uint32_t a;
    asm("{ .reg .u64 t; cvta.to.shared.u64 t, %1; cvt.u32.u64 %0, t; }" : "=r"(a) : "l"(p));
    return a;
}
__device__ __forceinline__ float gelu_exact(float v) {
    return 0.5f * v * (1.0f + erff(v * 0.7071067811865476f));
}
__device__ __forceinline__ uint32_t pack_h2(__half a, __half b) {
    return (uint32_t)__half_as_ushort(a) | ((uint32_t)__half_as_ushort(b) << 16);
}

__device__ __forceinline__ void cp16(uint32_t s, const void* g) {
    asm volatile("cp.async.cg.shared.global [%0], [%1], 16;" :: "r"(s), "l"(g));
}
__device__ __forceinline__ void cp_commit() { asm volatile("cp.async.commit_group;"); }
template<int N> __device__ __forceinline__ void cp_wait() {
    asm volatile("cp.async.wait_group %0;" :: "n"(N));
}
__device__ __forceinline__ void ldm_x4(uint32_t* r, uint32_t a) {
    asm volatile("ldmatrix.sync.aligned.m8n8.x4.shared.b16 {%0,%1,%2,%3}, [%4];"
                 : "=r"(r[0]), "=r"(r[1]), "=r"(r[2]), "=r"(r[3]) : "r"(a));
}
__device__ __forceinline__ void mma16816(float* c, const uint32_t* a, const uint32_t* b) {
    asm volatile(
        "mma.sync.aligned.m16n8k16.row.col.f32.f16.f16.f32 "
        "{%0,%1,%2,%3}, {%4,%5,%6,%7}, {%8,%9}, {%0,%1,%2,%3};"
        : "+f"(c[0]), "+f"(c[1]), "+f"(c[2]), "+f"(c[3])
        : "r"(a[0]), "r"(a[1]), "r"(a[2]), "r"(a[3]), "r"(b[0]), "r"(b[1]));
}
__device__ __forceinline__ void red_v2(float* addr, float v0, float v1) {
    asm volatile("red.global.add.v2.f32 [%0], {%1, %2};"
                 :: "l"(addr), "f"(v0), "f"(v1) : "memory");
}

// ---------------- router ----------------
__global__ void router_kernel(const float* __restrict__ x,
                              const float* __restrict__ Wr,
                              const float* __restrict__ br, int N) {
    int warp = (blockIdx.x * blockDim.x + threadIdx.x) >> 5;
    int lane = threadIdx.x & 31;
    if (warp >= N) return;
    const float* xr = x + (size_t)warp * DMODEL;
    float acc[8] = {0, 0, 0, 0, 0, 0, 0, 0};
    for (int d = lane; d < DMODEL; d += 32) {
        float xv = xr[d];
        float4 w0 = *(const float4*)(Wr + (size_t)d * 8);
        float4 w1 = *(const float4*)(Wr + (size_t)d * 8 + 4);
        acc[0] += xv * w0.x; acc[1] += xv * w0.y;
        acc[2] += xv * w0.z; acc[3] += xv * w0.w;
        acc[4] += xv * w1.x; acc[5] += xv * w1.y;
        acc[6] += xv * w1.z; acc[7] += xv * w1.w;
    }
    #pragma unroll
    for (int o = 16; o; o >>= 1)
        #pragma unroll
        for (int e = 0; e < 8; e++)
            acc[e] += __shfl_xor_sync(0xFFFFFFFFu, acc[e], o);
    if (lane == 0) {
        float l[8], p[8];
        float m = -1e30f;
        #pragma unroll
        for (int e = 0; e < 8; e++) { l[e] = acc[e] + br[e]; m = fmaxf(m, l[e]); }
        float s = 0.f;
        #pragma unroll
        for (int e = 0; e < 8; e++) { p[e] = expf(l[e] - m); s += p[e]; }
        float inv = 1.0f / s;
        #pragma unroll
        for (int e = 0; e < 8; e++) p[e] *= inv;
        int i1 = 0; float p1 = p[0];
        #pragma unroll
        for (int e = 1; e < 8; e++) if (p[e] > p1) { p1 = p[e]; i1 = e; }
        int i2 = -1; float p2 = -1.0f;
        #pragma unroll
        for (int e = 0; e < 8; e++) if (e != i1 && p[e] > p2) { p2 = p[e]; i2 = e; }
        float den = p1 + p2 + 1e-9f;
        g_ti[warp] = make_int2(i1, i2);
        g_tw[warp] = make_float2(p1 / den, p2 / den);
    }
}

// ---------------- dispatch: parallel Hillis-Steele scan, per-slot norm weights ----------------
__global__ void dispatch_kernel(int N, int cap) {
    const int T = 1024;
    int t = threadIdx.x;
    int slots = N * TOPK;
    int C = (slots + T - 1) / T;      // even (token pairs stay on one thread)
    __shared__ int sc[8][1024];
    __shared__ int stot[8];
    int cnt[8] = {0, 0, 0, 0, 0, 0, 0, 0};
    int s0 = t * C, s1 = min(s0 + C, slots);
    for (int s = s0; s < s1; s++) {
        int2 ti = g_ti[s >> 1];
        cnt[(s & 1) ? ti.y : ti.x]++;
    }
    int v[8];
    #pragma unroll
    for (int e = 0; e < 8; e++) { v[e] = cnt[e]; sc[e][t] = cnt[e]; }
    __syncthreads();
    // inclusive scan over 1024 threads, 8-wide payload
    #pragma unroll
    for (int off = 1; off < T; off <<= 1) {
        int u[8] = {0, 0, 0, 0, 0, 0, 0, 0};
        if (t >= off) {
            #pragma unroll
            for (int e = 0; e < 8; e++) u[e] = sc[e][t - off];
        }
        __syncthreads();
        #pragma unroll
        for (int e = 0; e < 8; e++) { v[e] += u[e]; sc[e][t] = v[e]; }
        __syncthreads();
    }
    if (t == T - 1) {
        #pragma unroll
        for (int e = 0; e < 8; e++) { stot[e] = v[e]; g_cnt[e] = min(v[e], cap); }
    }
    __syncthreads();
    int pos[8];
    #pragma unroll
    for (int e = 0; e < 8; e++) pos[e] = v[e] - cnt[e];   // exclusive prefix
    for (int s = s0; s < s1; s += 2) {
        int tok = s >> 1;
        int2 ti = g_ti[tok];
        float2 tw = g_tw[tok];
        int p0 = pos[ti.x]++;
        int p1 = pos[ti.y]++;
        bool k0 = p0 < cap, k1 = p1 < cap;
        float w0 = k0 ? tw.x : 0.0f;
        float w1 = k1 ? tw.y : 0.0f;
        float inv = 1.0f / (w0 + w1 + 1e-9f);
        if (k0) {
            int sl = ti.x * cap + p0;
            g_rowidx[sl] = tok; g_wn[sl] = w0 * inv;
        }
        if (k1) {
            int sl = ti.y * cap + p1;
            g_rowidx[sl] = tok; g_wn[sl] = w1 * inv;
        }
    }
    __syncthreads();
    for (int e = 0; e < 8; e++) {
        int c = min(stot[e], cap);
        for (int p = c + t; p < cap; p += T) g_rowidx[e * cap + p] = -1;
    }
}

// ---------------- weight convert+transpose: [e][R][C] f32 -> [e][C][R] fp16 ----------------
__global__ void wconvert_kernel(const float* __restrict__ src,
                                __half* __restrict__ dh, int R, int C) {
    int e = blockIdx.z;
    int c0 = blockIdx.x * 32, r0 = blockIdx.y * 32;
    __shared__ float t[32][33];
    int tx = threadIdx.x & 31, ty = threadIdx.x >> 5;
    const float* s = src + (size_t)e * R * C;
    #pragma unroll
    for (int i = 0; i < 4; i++)
        t[ty + i * 8][tx] = s[(size_t)(r0 + ty + i * 8) * C + c0 + tx];
    __syncthreads();
    size_t ob = (size_t)e * C * R;
    #pragma unroll
    for (int i = 0; i < 4; i++) {
        int c = c0 + ty + i * 8;
        float v = t[tx][ty + i * 8];
        dh[ob + (size_t)c * R + r0 + tx] = __float2half_rn(v);
    }
}

// ---------------- gather: tokens -> fp16 plane ----------------
__global__ void gather_kernel(const float* __restrict__ x, __half* __restrict__ Ah) {
    int gid = blockIdx.x * 256 + threadIdx.x;
    int row = gid >> 7, j = gid & 127;
    int tok = g_rowidx[row];
    float4 v = make_float4(0, 0, 0, 0);
    if (tok >= 0) v = ((const float4*)(x + (size_t)tok * DMODEL))[j];
    uint2 ph = make_uint2(pack_h2(__float2half_rn(v.x), __float2half_rn(v.y)),
                          pack_h2(__float2half_rn(v.z), __float2half_rn(v.w)));
    ((uint2*)(Ah + (size_t)row * DMODEL))[j] = ph;
}

// ---------------- fp16 mma.sync GEMM: tile 128x256, K-stage 32, 5-stage cp.async ----------------
#define RSTR 80
#define A_PL (128 * RSTR)          // 10240
#define B_PL (256 * RSTR)          // 20480
#define ST_A  0
#define ST_B  (A_PL)
#define ST_SZ (A_PL + B_PL)        // 30720
#define NST 5
#define SMEM_TOT (NST * ST_SZ)     // 153600

template<int KTOT, int NF, bool G1>
__global__ void __launch_bounds__(256, 1)
gemm_mma(const __half* __restrict__ Ah, const __half* __restrict__ Bh,
         const float* __restrict__ bias,
         __half* __restrict__ Oh, float* __restrict__ Of, int cap, int tpe) {
    int e = blockIdx.y / tpe, mt = blockIdx.y % tpe;
    if (mt * 128 >= g_cnt[e]) return;
    const int row0 = mt * 128;
    const int n0 = blockIdx.x * 256;
    extern __shared__ char sm[];
    const uint32_t sb = s2u(sm);
    const int tid = threadIdx.x;
    const int wid = tid >> 5, lane = tid & 31;
    const int wm = wid >> 2, wn = wid & 3;

    const size_t arow0 = (size_t)e * cap + row0;
    const __half* pA = Ah + arow0 * KTOT;
    const __half* pB = Bh + ((size_t)e * NF + n0) * KTOT;

    auto load_stage = [&](int buf, int kbase) {
        uint32_t sbase = sb + buf * ST_SZ;
        #pragma unroll
        for (int j = 0; j < 2; j++) {               // A: 512 16B-chunks
            int idx = j * 256 + tid;
            int r = idx >> 2, c = idx & 3;
            cp16(sbase + ST_A + r * RSTR + c * 16, pA + (size_t)r * KTOT + kbase + c * 8);
        }
        #pragma unroll
        for (int j = 0; j < 4; j++) {               // B: 1024 16B-chunks
            int idx = j * 256 + tid;
            int r = idx >> 2, c = idx & 3;
            cp16(sbase + ST_B + r * RSTR + c * 16, pB + (size_t)r * KTOT + kbase + c * 8);
        }
    };

    float acc[4][8][4];
    #pragma unroll
    for (int i = 0; i < 4; i++)
        #pragma unroll
        for (int j = 0; j < 8; j++)
            #pragma unroll
            for (int q = 0; q < 4; q++) acc[i][j][q] = 0.f;

    const uint32_t aAddr = (uint32_t)(wm * 64 + (lane & 15)) * RSTR + (lane >> 4) * 16;
    const uint32_t bAddr = (uint32_t)(wn * 64 + ((lane >> 4) & 1) * 8 + (lane & 7)) * RSTR
                           + ((lane >> 3) & 1) * 16;

    const int NK = KTOT / 32;
    load_stage(0, 0);  cp_commit();
    load_stage(1, 32); cp_commit();
    load_stage(2, 64); cp_commit();
    load_stage(3, 96); cp_commit();

    for (int s = 0; s < NK; s++) {
        cp_wait<3>();
        __syncthreads();

        uint32_t sbase = sb + (s % NST) * ST_SZ;
        #pragma unroll
        for (int kk = 0; kk < 2; kk++) {
            uint32_t koff = kk * 32;
            uint32_t ah[4][4], bh[4][4];
            #pragma unroll
            for (int mi = 0; mi < 4; mi++)
                ldm_x4(ah[mi], sbase + ST_A + aAddr + mi * (16 * RSTR) + koff);
            #pragma unroll
            for (int nq = 0; nq < 4; nq++)
                ldm_x4(bh[nq], sbase + ST_B + bAddr + nq * (16 * RSTR) + koff);
            #pragma unroll
            for (int mi = 0; mi < 4; mi++)
                #pragma unroll
                for (int nq = 0; nq < 4; nq++) {
                    mma16816(acc[mi][2 * nq],     ah[mi], bh[nq]);
                    mma16816(acc[mi][2 * nq + 1], ah[mi], bh[nq] + 2);
                }
        }

        if (s + 4 < NK) load_stage((s + 4) % NST, (s + 4) * 32);
        cp_commit();
    }

    // ---------------- epilogue (G1 direct stores; G2 fused combine via v2 reductions) ----------------
    const int colbase = n0 + wn * 64 + (lane & 3) * 2;
    const int rowbase = wm * 64 + (lane >> 2);
    float2 bvv[8];
    #pragma unroll
    for (int ni = 0; ni < 8; ni++)
        bvv[ni] = *(const float2*)(bias + (size_t)e * NF + colbase + ni * 8);
    #pragma unroll
    for (int mi = 0; mi < 4; mi++) {
        #pragma unroll
        for (int half = 0; half < 2; half++) {
            int r = rowbase + mi * 16 + half * 8;
            size_t grow = arow0 + r;
            if (G1) {
                #pragma unroll
                for (int ni = 0; ni < 8; ni++) {
                    int col = colbase + ni * 8;
                    float g0 = gelu_exact(acc[mi][ni][half * 2 + 0] + bvv[ni].x);
                    float g1 = gelu_exact(acc[mi][ni][half * 2 + 1] + bvv[ni].y);
                    *(uint32_t*)(Oh + grow * NF + col) =
                        pack_h2(__float2half_rn(g0), __float2half_rn(g1));
                }
            } else {
                int tok = g_rowidx[grow];
                if (tok >= 0) {
                    float w = g_wn[grow];
                    float* op = Of + (size_t)tok * DMODEL;
                    #pragma unroll
                    for (int ni = 0; ni < 8; ni++) {
                        int col = colbase + ni * 8;
                        float v0 = w * (acc[mi][ni][half * 2 + 0] + bvv[ni].x);
                        float v1 = w * (acc[mi][ni][half * 2 + 1] + bvv[ni].y);
                        red_v2(op + col, v0, v1);
                    }
                }
            }
        }
    }
}

// ---------------- launch ----------------
extern "C" void kernel_launch(void* const* d_in, const int* in_sizes, int n_in,
                              void* d_out, int out_size) {
    const float* x  = (const float*)d_in[0];
    const float* Wr = (const float*)d_in[1];
    const float* br = (const float*)d_in[2];
    const float* W1 = (const float*)d_in[3];
    const float* b1 = (const float*)d_in[4];
    const float* W2 = (const float*)d_in[5];
    const float* b2 = (const float*)d_in[6];
    float* out = (float*)d_out;

    int N = in_sizes[0] / DMODEL;
    if (N > NMAX) N = NMAX;
    int cap = (5 * N + 15) / 16;
    if (cap > CAPMAX) cap = CAPMAX;
    int tpe = (cap + 127) / 128;

    void *a1h, *hh, *w1h, *w2h;
    cudaGetSymbolAddress(&a1h, g_A1h);
    cudaGetSymbolAddress(&hh,  g_Hh);
    cudaGetSymbolAddress(&w1h, g_W1h); cudaGetSymbolAddress(&w2h, g_W2h);

    cudaFuncSetAttribute(gemm_mma<DMODEL, DFF, true>,
                         cudaFuncAttributeMaxDynamicSharedMemorySize, SMEM_TOT);
    cudaFuncSetAttribute(gemm_mma<DFF, DMODEL, false>,
                         cudaFuncAttributeMaxDynamicSharedMemorySize, SMEM_TOT);

    // side stream for weight conversion (event fork/join: graph-capture safe)
    cudaStream_t s2;
    cudaStreamCreateWithFlags(&s2, cudaStreamNonBlocking);
    cudaEvent_t ev0, ev1;
    cudaEventCreateWithFlags(&ev0, cudaEventDisableTiming);
    cudaEventCreateWithFlags(&ev1, cudaEventDisableTiming);

    cudaMemsetAsync(out, 0, (size_t)out_size * sizeof(float));
    cudaEventRecord(ev0, 0);
    cudaStreamWaitEvent(s2, ev0, 0);
    wconvert_kernel<<<dim3(DFF / 32, DMODEL / 32, NEXP), 256, 0, s2>>>(
        W1, (__half*)w1h, DMODEL, DFF);
    wconvert_kernel<<<dim3(DMODEL / 32, DFF / 32, NEXP), 256, 0, s2>>>(
        W2, (__half*)w2h, DFF, DMODEL);
    cudaEventRecord(ev1, s2);

    router_kernel<<<(N * 32 + 255) / 256, 256>>>(x, Wr, br, N);
    dispatch_kernel<<<1, 1024>>>(N, cap);
    gather_kernel<<<(NEXP * cap * 128) / 256, 256>>>(x, (__half*)a1h);

    cudaStreamWaitEvent(0, ev1, 0);

    dim3 g1(DFF / 256, NEXP * tpe);
    gemm_mma<DMODEL, DFF, true><<<g1, 256, SMEM_TOT>>>(
        (const __half*)a1h, (const __half*)w1h, b1,
        (__half*)hh, nullptr, cap, tpe);

    dim3 g2(DMODEL / 256, NEXP * tpe);
    gemm_mma<DFF, DMODEL, false><<<g2, 256, SMEM_TOT>>>(
        (const __half*)hh, (const __half*)w2h, b2,
        nullptr, out, cap, tpe);
}

// round 11
// speedup vs baseline: 1.2754x; 1.1227x over previous
#include <cuda_runtime.h>
#include <cuda_fp16.h>
#include <cstdint>

#define DMODEL 512
#define DFF 2048
#define NEXP 8
#define TOPK 2
#define NMAX 32768
#define CAPMAX 10240
#define EROWS (NEXP * CAPMAX)
#define NB 128                 // dispatch blocks (N/256)

typedef unsigned long long ull;

// ---------------- scratch ----------------
__device__ __align__(1024) __half g_A1h[(size_t)EROWS * DMODEL];
__device__ __align__(1024) __half g_Hh [(size_t)EROWS * DFF];
__device__ __align__(1024) __half g_W1h[(size_t)NEXP * DFF * DMODEL];   // [e][n][k]
__device__ __align__(1024) __half g_W2h[(size_t)NEXP * DMODEL * DFF];   // [e][n][k]
__device__ int    g_rowidx[EROWS];     // slot -> token (-1 pad)
__device__ float  g_wn[EROWS];         // slot -> normalized combine weight
__device__ int2   g_ti[NMAX];
__device__ float2 g_tw[NMAX];
__device__ int    g_cnt[NEXP];
__device__ int    g_blkcnt[NB * NEXP];
__device__ int    g_blkoff[NB * NEXP];

// ---------------- helpers ----------------
__device__ __forceinline__ uint32_t s2u(const void* p) {
    uint32_t a;
    asm("{ .reg .u64 t; cvta.to.shared.u64 t, %1; cvt.u32.u64 %0, t; }" : "=r"(a) : "l"(p));
    return a;
}
__device__ __forceinline__ float gelu_exact(float v) {
    return 0.5f * v * (1.0f + erff(v * 0.7071067811865476f));
}
__device__ __forceinline__ uint32_t pack_h2(__half a, __half b) {
    return (uint32_t)__half_as_ushort(a) | ((uint32_t)__half_as_ushort(b) << 16);
}

__device__ __forceinline__ void cp16(uint32_t s, const void* g) {
    asm volatile("cp.async.cg.shared.global [%0], [%1], 16;" :: "r"(s), "l"(g));
}
__device__ __forceinline__ void cp_commit() { asm volatile("cp.async.commit_group;"); }
template<int N> __device__ __forceinline__ void cp_wait() {
    asm volatile("cp.async.wait_group %0;" :: "n"(N));
}
__device__ __forceinline__ void ldm_x4(uint32_t* r, uint32_t a) {
    asm volatile("ldmatrix.sync.aligned.m8n8.x4.shared.b16 {%0,%1,%2,%3}, [%4];"
                 : "=r"(r[0]), "=r"(r[1]), "=r"(r[2]), "=r"(r[3]) : "r"(a));
}
__device__ __forceinline__ void mma16816(float* c, const uint32_t* a, const uint32_t* b) {
    asm volatile(
        "mma.sync.aligned.m16n8k16.row.col.f32.f16.f16.f32 "
        "{%0,%1,%2,%3}, {%4,%5,%6,%7}, {%8,%9}, {%0,%1,%2,%3};"
        : "+f"(c[0]), "+f"(c[1]), "+f"(c[2]), "+f"(c[3])
        : "r"(a[0]), "r"(a[1]), "r"(a[2]), "r"(a[3]), "r"(b[0]), "r"(b[1]));
}
__device__ __forceinline__ void red_v2(float* addr, float v0, float v1) {
    asm volatile("red.global.add.v2.f32 [%0], {%1, %2};"
                 :: "l"(addr), "f"(v0), "f"(v1) : "memory");
}

// ---------------- router ----------------
__global__ void router_kernel(const float* __restrict__ x,
                              const float* __restrict__ Wr,
                              const float* __restrict__ br, int N) {
    int warp = (blockIdx.x * blockDim.x + threadIdx.x) >> 5;
    int lane = threadIdx.x & 31;
    if (warp >= N) return;
    const float* xr = x + (size_t)warp * DMODEL;
    float acc[8] = {0, 0, 0, 0, 0, 0, 0, 0};
    for (int d = lane; d < DMODEL; d += 32) {
        float xv = xr[d];
        float4 w0 = *(const float4*)(Wr + (size_t)d * 8);
        float4 w1 = *(const float4*)(Wr + (size_t)d * 8 + 4);
        acc[0] += xv * w0.x; acc[1] += xv * w0.y;
        acc[2] += xv * w0.z; acc[3] += xv * w0.w;
        acc[4] += xv * w1.x; acc[5] += xv * w1.y;
        acc[6] += xv * w1.z; acc[7] += xv * w1.w;
    }
    #pragma unroll
    for (int o = 16; o; o >>= 1)
        #pragma unroll
        for (int e = 0; e < 8; e++)
            acc[e] += __shfl_xor_sync(0xFFFFFFFFu, acc[e], o);
    if (lane == 0) {
        float l[8], p[8];
        float m = -1e30f;
        #pragma unroll
        for (int e = 0; e < 8; e++) { l[e] = acc[e] + br[e]; m = fmaxf(m, l[e]); }
        float s = 0.f;
        #pragma unroll
        for (int e = 0; e < 8; e++) { p[e] = expf(l[e] - m); s += p[e]; }
        float inv = 1.0f / s;
        #pragma unroll
        for (int e = 0; e < 8; e++) p[e] *= inv;
        int i1 = 0; float p1 = p[0];
        #pragma unroll
        for (int e = 1; e < 8; e++) if (p[e] > p1) { p1 = p[e]; i1 = e; }
        int i2 = -1; float p2 = -1.0f;
        #pragma unroll
        for (int e = 0; e < 8; e++) if (e != i1 && p[e] > p2) { p2 = p[e]; i2 = e; }
        float den = p1 + p2 + 1e-9f;
        g_ti[warp] = make_int2(i1, i2);
        g_tw[warp] = make_float2(p1 / den, p2 / den);
    }
}

// ---------------- dispatch phase 1: per-block expert histograms ----------------
__global__ void count_kernel(int N) {
    __shared__ int sc[8];
    int t = threadIdx.x, b = blockIdx.x;
    if (t < 8) sc[t] = 0;
    __syncthreads();
    int tok = b * 256 + t;
    if (tok < N) {
        int2 ti = g_ti[tok];
        atomicAdd(&sc[ti.x], 1);
        atomicAdd(&sc[ti.y], 1);
    }
    __syncthreads();
    if (t < 8) g_blkcnt[b * 8 + t] = sc[t];
}

// ---------------- dispatch phase 2: scan block histograms ----------------
__global__ void scan_kernel(int cap) {      // 1 block, NB threads
    __shared__ int sm[NB][8];
    int t = threadIdx.x;
    int own[8], v[8];
    #pragma unroll
    for (int e = 0; e < 8; e++) { own[e] = g_blkcnt[t * 8 + e]; v[e] = own[e]; sm[t][e] = own[e]; }
    __syncthreads();
    #pragma unroll
    for (int off = 1; off < NB; off <<= 1) {
        int u[8] = {0, 0, 0, 0, 0, 0, 0, 0};
        if (t >= off) {
            #pragma unroll
            for (int e = 0; e < 8; e++) u[e] = sm[t - off][e];
        }
        __syncthreads();
        #pragma unroll
        for (int e = 0; e < 8; e++) { v[e] += u[e]; sm[t][e] = v[e]; }
        __syncthreads();
    }
    #pragma unroll
    for (int e = 0; e < 8; e++) g_blkoff[t * 8 + e] = v[e] - own[e];
    if (t == NB - 1) {
        #pragma unroll
        for (int e = 0; e < 8; e++) g_cnt[e] = min(v[e], cap);
    }
}

// ---------------- dispatch phase 3: scatter slots (thread = token, order preserved) ----------------
__global__ void scatter_kernel(int N, int cap) {
    __shared__ int sm[256][8];
    int t = threadIdx.x, b = blockIdx.x;
    int tok = b * 256 + t;
    int2 ti = make_int2(0, 0);
    float2 tw = make_float2(0.f, 0.f);
    int cnt[8] = {0, 0, 0, 0, 0, 0, 0, 0};
    bool valid = tok < N;
    if (valid) {
        ti = g_ti[tok]; tw = g_tw[tok];
        cnt[ti.x]++; cnt[ti.y]++;
    }
    int v[8];
    #pragma unroll
    for (int e = 0; e < 8; e++) { v[e] = cnt[e]; sm[t][e] = cnt[e]; }
    __syncthreads();
    #pragma unroll
    for (int off = 1; off < 256; off <<= 1) {
        int u[8] = {0, 0, 0, 0, 0, 0, 0, 0};
        if (t >= off) {
            #pragma unroll
            for (int e = 0; e < 8; e++) u[e] = sm[t - off][e];
        }
        __syncthreads();
        #pragma unroll
        for (int e = 0; e < 8; e++) { v[e] += u[e]; sm[t][e] = v[e]; }
        __syncthreads();
    }
    if (valid) {
        // exclusive thread prefix + block offset
        int p0 = v[ti.x] - cnt[ti.x] + g_blkoff[b * 8 + ti.x];
        int p1 = v[ti.y] - cnt[ti.y] + g_blkoff[b * 8 + ti.y];
        bool k0 = p0 < cap, k1 = p1 < cap;
        float w0 = k0 ? tw.x : 0.0f;
        float w1 = k1 ? tw.y : 0.0f;
        float inv = 1.0f / (w0 + w1 + 1e-9f);
        if (k0) {
            int sl = ti.x * cap + p0;
            g_rowidx[sl] = tok; g_wn[sl] = w0 * inv;
        }
        if (k1) {
            int sl = ti.y * cap + p1;
            g_rowidx[sl] = tok; g_wn[sl] = w1 * inv;
        }
    }
}

// ---------------- weight convert+transpose: [e][R][C] f32 -> [e][C][R] fp16 ----------------
__global__ void wconvert_kernel(const float* __restrict__ src,
                                __half* __restrict__ dh, int R, int C) {
    int e = blockIdx.z;
    int c0 = blockIdx.x * 32, r0 = blockIdx.y * 32;
    __shared__ float t[32][33];
    int tx = threadIdx.x & 31, ty = threadIdx.x >> 5;
    const float* s = src + (size_t)e * R * C;
    #pragma unroll
    for (int i = 0; i < 4; i++)
        t[ty + i * 8][tx] = s[(size_t)(r0 + ty + i * 8) * C + c0 + tx];
    __syncthreads();
    size_t ob = (size_t)e * C * R;
    #pragma unroll
    for (int i = 0; i < 4; i++) {
        int c = c0 + ty + i * 8;
        float v = t[tx][ty + i * 8];
        dh[ob + (size_t)c * R + r0 + tx] = __float2half_rn(v);
    }
}

// ---------------- gather: tokens -> fp16 plane ----------------
__global__ void gather_kernel(const float* __restrict__ x, __half* __restrict__ Ah) {
    int gid = blockIdx.x * 256 + threadIdx.x;
    int row = gid >> 7, j = gid & 127;
    int tok = g_rowidx[row];
    float4 v = make_float4(0, 0, 0, 0);
    if (tok >= 0) v = ((const float4*)(x + (size_t)tok * DMODEL))[j];
    uint2 ph = make_uint2(pack_h2(__float2half_rn(v.x), __float2half_rn(v.y)),
                          pack_h2(__float2half_rn(v.z), __float2half_rn(v.w)));
    ((uint2*)(Ah + (size_t)row * DMODEL))[j] = ph;
}

// ---------------- fp16 mma.sync GEMM: tile 128x256, K-stage 32, 5-stage cp.async ----------------
#define RSTR 80
#define A_PL (128 * RSTR)          // 10240
#define B_PL (256 * RSTR)          // 20480
#define ST_A  0
#define ST_B  (A_PL)
#define ST_SZ (A_PL + B_PL)        // 30720
#define NST 5
#define SMEM_TOT (NST * ST_SZ)     // 153600

template<int KTOT, int NF, bool G1>
__global__ void __launch_bounds__(256, 1)
gemm_mma(const __half* __restrict__ Ah, const __half* __restrict__ Bh,
         const float* __restrict__ bias,
         __half* __restrict__ Oh, float* __restrict__ Of, int cap, int tpe) {
    int e = blockIdx.y / tpe, mt = blockIdx.y % tpe;
    if (mt * 128 >= g_cnt[e]) return;
    const int row0 = mt * 128;
    const int n0 = blockIdx.x * 256;
    extern __shared__ char sm[];
    const uint32_t sb = s2u(sm);
    const int tid = threadIdx.x;
    const int wid = tid >> 5, lane = tid & 31;
    const int wm = wid >> 2, wn = wid & 3;

    const size_t arow0 = (size_t)e * cap + row0;
    const __half* pA = Ah + arow0 * KTOT;
    const __half* pB = Bh + ((size_t)e * NF + n0) * KTOT;

    auto load_stage = [&](int buf, int kbase) {
        uint32_t sbase = sb + buf * ST_SZ;
        #pragma unroll
        for (int j = 0; j < 2; j++) {               // A: 512 16B-chunks
            int idx = j * 256 + tid;
            int r = idx >> 2, c = idx & 3;
            cp16(sbase + ST_A + r * RSTR + c * 16, pA + (size_t)r * KTOT + kbase + c * 8);
        }
        #pragma unroll
        for (int j = 0; j < 4; j++) {               // B: 1024 16B-chunks
            int idx = j * 256 + tid;
            int r = idx >> 2, c = idx & 3;
            cp16(sbase + ST_B + r * RSTR + c * 16, pB + (size_t)r * KTOT + kbase + c * 8);
        }
    };

    float acc[4][8][4];
    #pragma unroll
    for (int i = 0; i < 4; i++)
        #pragma unroll
        for (int j = 0; j < 8; j++)
            #pragma unroll
            for (int q = 0; q < 4; q++) acc[i][j][q] = 0.f;

    const uint32_t aAddr = (uint32_t)(wm * 64 + (lane & 15)) * RSTR + (lane >> 4) * 16;
    const uint32_t bAddr = (uint32_t)(wn * 64 + ((lane >> 4) & 1) * 8 + (lane & 7)) * RSTR
                           + ((lane >> 3) & 1) * 16;

    const int NK = KTOT / 32;
    load_stage(0, 0);  cp_commit();
    load_stage(1, 32); cp_commit();
    load_stage(2, 64); cp_commit();
    load_stage(3, 96); cp_commit();

    for (int s = 0; s < NK; s++) {
        cp_wait<3>();
        __syncthreads();

        uint32_t sbase = sb + (s % NST) * ST_SZ;
        #pragma unroll
        for (int kk = 0; kk < 2; kk++) {
            uint32_t koff = kk * 32;
            uint32_t ah[4][4], bh[4][4];
            #pragma unroll
            for (int mi = 0; mi < 4; mi++)
                ldm_x4(ah[mi], sbase + ST_A + aAddr + mi * (16 * RSTR) + koff);
            #pragma unroll
            for (int nq = 0; nq < 4; nq++)
                ldm_x4(bh[nq], sbase + ST_B + bAddr + nq * (16 * RSTR) + koff);
            #pragma unroll
            for (int mi = 0; mi < 4; mi++)
                #pragma unroll
                for (int nq = 0; nq < 4; nq++) {
                    mma16816(acc[mi][2 * nq],     ah[mi], bh[nq]);
                    mma16816(acc[mi][2 * nq + 1], ah[mi], bh[nq] + 2);
                }
        }

        if (s + 4 < NK) load_stage((s + 4) % NST, (s + 4) * 32);
        cp_commit();
    }

    // ---------------- epilogue (G1 direct stores; G2 fused combine via v2 reductions) ----------------
    const int colbase = n0 + wn * 64 + (lane & 3) * 2;
    const int rowbase = wm * 64 + (lane >> 2);
    float2 bvv[8];
    #pragma unroll
    for (int ni = 0; ni < 8; ni++)
        bvv[ni] = *(const float2*)(bias + (size_t)e * NF + colbase + ni * 8);
    #pragma unroll
    for (int mi = 0; mi < 4; mi++) {
        #pragma unroll
        for (int half = 0; half < 2; half++) {
            int r = rowbase + mi * 16 + half * 8;
            size_t grow = arow0 + r;
            if (G1) {
                #pragma unroll
                for (int ni = 0; ni < 8; ni++) {
                    int col = colbase + ni * 8;
                    float g0 = gelu_exact(acc[mi][ni][half * 2 + 0] + bvv[ni].x);
                    float g1 = gelu_exact(acc[mi][ni][half * 2 + 1] + bvv[ni].y);
                    *(uint32_t*)(Oh + grow * NF + col) =
                        pack_h2(__float2half_rn(g0), __float2half_rn(g1));
                }
            } else {
                int tok = g_rowidx[grow];
                if (tok >= 0) {
                    float w = g_wn[grow];
                    float* op = Of + (size_t)tok * DMODEL;
                    #pragma unroll
                    for (int ni = 0; ni < 8; ni++) {
                        int col = colbase + ni * 8;
                        float v0 = w * (acc[mi][ni][half * 2 + 0] + bvv[ni].x);
                        float v1 = w * (acc[mi][ni][half * 2 + 1] + bvv[ni].y);
                        red_v2(op + col, v0, v1);
                    }
                }
            }
        }
    }
}

// ---------------- launch ----------------
extern "C" void kernel_launch(void* const* d_in, const int* in_sizes, int n_in,
                              void* d_out, int out_size) {
    const float* x  = (const float*)d_in[0];
    const float* Wr = (const float*)d_in[1];
    const float* br = (const float*)d_in[2];
    const float* W1 = (const float*)d_in[3];
    const float* b1 = (const float*)d_in[4];
    const float* W2 = (const float*)d_in[5];
    const float* b2 = (const float*)d_in[6];
    float* out = (float*)d_out;

    int N = in_sizes[0] / DMODEL;
    if (N > NMAX) N = NMAX;
    int cap = (5 * N + 15) / 16;
    if (cap > CAPMAX) cap = CAPMAX;
    int tpe = (cap + 127) / 128;
    int nblk = (N + 255) / 256;          // = NB for N=32768

    void *a1h, *hh, *w1h, *w2h, *ridx;
    cudaGetSymbolAddress(&a1h, g_A1h);
    cudaGetSymbolAddress(&hh,  g_Hh);
    cudaGetSymbolAddress(&w1h, g_W1h); cudaGetSymbolAddress(&w2h, g_W2h);
    cudaGetSymbolAddress(&ridx, g_rowidx);

    cudaFuncSetAttribute(gemm_mma<DMODEL, DFF, true>,
                         cudaFuncAttributeMaxDynamicSharedMemorySize, SMEM_TOT);
    cudaFuncSetAttribute(gemm_mma<DFF, DMODEL, false>,
                         cudaFuncAttributeMaxDynamicSharedMemorySize, SMEM_TOT);

    // side stream for weight conversion (event fork/join: graph-capture safe)
    cudaStream_t s2;
    cudaStreamCreateWithFlags(&s2, cudaStreamNonBlocking);
    cudaEvent_t ev0, ev1;
    cudaEventCreateWithFlags(&ev0, cudaEventDisableTiming);
    cudaEventCreateWithFlags(&ev1, cudaEventDisableTiming);

    cudaMemsetAsync(out, 0, (size_t)out_size * sizeof(float));
    cudaMemsetAsync(ridx, 0xFF, (size_t)EROWS * sizeof(int));   // all slots -> -1
    cudaEventRecord(ev0, 0);
    cudaStreamWaitEvent(s2, ev0, 0);
    wconvert_kernel<<<dim3(DFF / 32, DMODEL / 32, NEXP), 256, 0, s2>>>(
        W1, (__half*)w1h, DMODEL, DFF);
    wconvert_kernel<<<dim3(DMODEL / 32, DFF / 32, NEXP), 256, 0, s2>>>(
        W2, (__half*)w2h, DFF, DMODEL);
    cudaEventRecord(ev1, s2);

    router_kernel<<<(N * 32 + 255) / 256, 256>>>(x, Wr, br, N);
    count_kernel<<<nblk, 256>>>(N);
    scan_kernel<<<1, NB>>>(cap);
    scatter_kernel<<<nblk, 256>>>(N, cap);
    gather_kernel<<<(NEXP * cap * 128) / 256, 256>>>(x, (__half*)a1h);

    cudaStreamWaitEvent(0, ev1, 0);

    dim3 g1(DFF / 256, NEXP * tpe);
    gemm_mma<DMODEL, DFF, true><<<g1, 256, SMEM_TOT>>>(
        (const __half*)a1h, (const __half*)w1h, b1,
        (__half*)hh, nullptr, cap, tpe);

    dim3 g2(DMODEL / 256, NEXP * tpe);
    gemm_mma<DFF, DMODEL, false><<<g2, 256, SMEM_TOT>>>(
        (const __half*)hh, (const __half*)w2h, b2,
        nullptr, out, cap, tpe);
}

// round 12
// speedup vs baseline: 1.3632x; 1.0688x over previous
#include <cuda_runtime.h>
#include <cuda_fp16.h>
#include <cstdint>

#define DMODEL 512
#define DFF 2048
#define NEXP 8
#define TOPK 2
#define NMAX 32768
#define CAPMAX 10240
#define EROWS (NEXP * CAPMAX)
#define NB 128                 // dispatch blocks (N/256)

typedef unsigned long long ull;

// ---------------- scratch ----------------
__device__ __align__(1024) __half g_A1h[(size_t)EROWS * DMODEL];
__device__ __align__(1024) __half g_Hh [(size_t)EROWS * DFF];
__device__ __align__(1024) __half g_W1h[(size_t)NEXP * DFF * DMODEL];   // [e][n][k]
__device__ __align__(1024) __half g_W2h[(size_t)NEXP * DMODEL * DFF];   // [e][n][k]
__device__ int    g_rowidx[EROWS];     // slot -> token (-1 pad)
__device__ float  g_wn[EROWS];         // slot -> normalized combine weight
__device__ int2   g_ti[NMAX];
__device__ float2 g_tw[NMAX];
__device__ int    g_cnt[NEXP];
__device__ int    g_blkcnt[NB * NEXP];
__device__ int    g_blkoff[NB * NEXP];

// ---------------- helpers ----------------
__device__ __forceinline__ uint32_t s2u(const void* p) {
    uint32_t a;
    asm("{ .reg .u64 t; cvta.to.shared.u64 t, %1; cvt.u32.u64 %0, t; }" : "=r"(a) : "l"(p));
    return a;
}
__device__ __forceinline__ float gelu_exact(float v) {
    return 0.5f * v * (1.0f + erff(v * 0.7071067811865476f));
}
__device__ __forceinline__ uint32_t pack_h2(__half a, __half b) {
    return (uint32_t)__half_as_ushort(a) | ((uint32_t)__half_as_ushort(b) << 16);
}

__device__ __forceinline__ void cp16(uint32_t s, const void* g) {
    asm volatile("cp.async.cg.shared.global [%0], [%1], 16;" :: "r"(s), "l"(g));
}
__device__ __forceinline__ void cp_commit() { asm volatile("cp.async.commit_group;"); }
template<int N> __device__ __forceinline__ void cp_wait() {
    asm volatile("cp.async.wait_group %0;" :: "n"(N));
}
__device__ __forceinline__ void ldm_x4(uint32_t* r, uint32_t a) {
    asm volatile("ldmatrix.sync.aligned.m8n8.x4.shared.b16 {%0,%1,%2,%3}, [%4];"
                 : "=r"(r[0]), "=r"(r[1]), "=r"(r[2]), "=r"(r[3]) : "r"(a));
}
__device__ __forceinline__ void mma16816(float* c, const uint32_t* a, const uint32_t* b) {
    asm volatile(
        "mma.sync.aligned.m16n8k16.row.col.f32.f16.f16.f32 "
        "{%0,%1,%2,%3}, {%4,%5,%6,%7}, {%8,%9}, {%0,%1,%2,%3};"
        : "+f"(c[0]), "+f"(c[1]), "+f"(c[2]), "+f"(c[3])
        : "r"(a[0]), "r"(a[1]), "r"(a[2]), "r"(a[3]), "r"(b[0]), "r"(b[1]));
}
__device__ __forceinline__ void red_v2(float* addr, float v0, float v1) {
    asm volatile("red.global.add.v2.f32 [%0], {%1, %2};"
                 :: "l"(addr), "f"(v0), "f"(v1) : "memory");
}

// ---------------- router ----------------
__global__ void router_kernel(const float* __restrict__ x,
                              const float* __restrict__ Wr,
                              const float* __restrict__ br, int N) {
    int warp = (blockIdx.x * blockDim.x + threadIdx.x) >> 5;
    int lane = threadIdx.x & 31;
    if (warp >= N) return;
    const float* xr = x + (size_t)warp * DMODEL;
    float acc[8] = {0, 0, 0, 0, 0, 0, 0, 0};
    for (int d = lane; d < DMODEL; d += 32) {
        float xv = xr[d];
        float4 w0 = *(const float4*)(Wr + (size_t)d * 8);
        float4 w1 = *(const float4*)(Wr + (size_t)d * 8 + 4);
        acc[0] += xv * w0.x; acc[1] += xv * w0.y;
        acc[2] += xv * w0.z; acc[3] += xv * w0.w;
        acc[4] += xv * w1.x; acc[5] += xv * w1.y;
        acc[6] += xv * w1.z; acc[7] += xv * w1.w;
    }
    #pragma unroll
    for (int o = 16; o; o >>= 1)
        #pragma unroll
        for (int e = 0; e < 8; e++)
            acc[e] += __shfl_xor_sync(0xFFFFFFFFu, acc[e], o);
    if (lane == 0) {
        float l[8], p[8];
        float m = -1e30f;
        #pragma unroll
        for (int e = 0; e < 8; e++) { l[e] = acc[e] + br[e]; m = fmaxf(m, l[e]); }
        float s = 0.f;
        #pragma unroll
        for (int e = 0; e < 8; e++) { p[e] = expf(l[e] - m); s += p[e]; }
        float inv = 1.0f / s;
        #pragma unroll
        for (int e = 0; e < 8; e++) p[e] *= inv;
        int i1 = 0; float p1 = p[0];
        #pragma unroll
        for (int e = 1; e < 8; e++) if (p[e] > p1) { p1 = p[e]; i1 = e; }
        int i2 = -1; float p2 = -1.0f;
        #pragma unroll
        for (int e = 0; e < 8; e++) if (e != i1 && p[e] > p2) { p2 = p[e]; i2 = e; }
        float den = p1 + p2 + 1e-9f;
        g_ti[warp] = make_int2(i1, i2);
        g_tw[warp] = make_float2(p1 / den, p2 / den);
    }
}

// ---------------- dispatch phase 1: per-block expert histograms ----------------
__global__ void count_kernel(int N) {
    __shared__ int sc[8];
    int t = threadIdx.x, b = blockIdx.x;
    if (t < 8) sc[t] = 0;
    __syncthreads();
    int tok = b * 256 + t;
    if (tok < N) {
        int2 ti = g_ti[tok];
        atomicAdd(&sc[ti.x], 1);
        atomicAdd(&sc[ti.y], 1);
    }
    __syncthreads();
    if (t < 8) g_blkcnt[b * 8 + t] = sc[t];
}

// ---------------- dispatch phase 2: scan block histograms ----------------
__global__ void scan_kernel(int cap) {      // 1 block, NB threads
    __shared__ int sm[NB][8];
    int t = threadIdx.x;
    int own[8], v[8];
    #pragma unroll
    for (int e = 0; e < 8; e++) { own[e] = g_blkcnt[t * 8 + e]; v[e] = own[e]; sm[t][e] = own[e]; }
    __syncthreads();
    #pragma unroll
    for (int off = 1; off < NB; off <<= 1) {
        int u[8] = {0, 0, 0, 0, 0, 0, 0, 0};
        if (t >= off) {
            #pragma unroll
            for (int e = 0; e < 8; e++) u[e] = sm[t - off][e];
        }
        __syncthreads();
        #pragma unroll
        for (int e = 0; e < 8; e++) { v[e] += u[e]; sm[t][e] = v[e]; }
        __syncthreads();
    }
    #pragma unroll
    for (int e = 0; e < 8; e++) g_blkoff[t * 8 + e] = v[e] - own[e];
    if (t == NB - 1) {
        #pragma unroll
        for (int e = 0; e < 8; e++) g_cnt[e] = min(v[e], cap);
    }
}

// ---------------- dispatch phase 3: scatter slots (thread = token, order preserved) ----------------
__global__ void scatter_kernel(int N, int cap) {
    __shared__ int sm[256][8];
    int t = threadIdx.x, b = blockIdx.x;
    int tok = b * 256 + t;
    int2 ti = make_int2(0, 0);
    float2 tw = make_float2(0.f, 0.f);
    int cnt[8] = {0, 0, 0, 0, 0, 0, 0, 0};
    bool valid = tok < N;
    if (valid) {
        ti = g_ti[tok]; tw = g_tw[tok];
        cnt[ti.x]++; cnt[ti.y]++;
    }
    int v[8];
    #pragma unroll
    for (int e = 0; e < 8; e++) { v[e] = cnt[e]; sm[t][e] = cnt[e]; }
    __syncthreads();
    #pragma unroll
    for (int off = 1; off < 256; off <<= 1) {
        int u[8] = {0, 0, 0, 0, 0, 0, 0, 0};
        if (t >= off) {
            #pragma unroll
            for (int e = 0; e < 8; e++) u[e] = sm[t - off][e];
        }
        __syncthreads();
        #pragma unroll
        for (int e = 0; e < 8; e++) { v[e] += u[e]; sm[t][e] = v[e]; }
        __syncthreads();
    }
    if (valid) {
        int p0 = v[ti.x] - cnt[ti.x] + g_blkoff[b * 8 + ti.x];
        int p1 = v[ti.y] - cnt[ti.y] + g_blkoff[b * 8 + ti.y];
        bool k0 = p0 < cap, k1 = p1 < cap;
        float w0 = k0 ? tw.x : 0.0f;
        float w1 = k1 ? tw.y : 0.0f;
        float inv = 1.0f / (w0 + w1 + 1e-9f);
        if (k0) {
            int sl = ti.x * cap + p0;
            g_rowidx[sl] = tok; g_wn[sl] = w0 * inv;
        }
        if (k1) {
            int sl = ti.y * cap + p1;
            g_rowidx[sl] = tok; g_wn[sl] = w1 * inv;
        }
    }
}

// ---------------- weight convert+transpose: [e][R][C] f32 -> [e][C][R] fp16 ----------------
__global__ void wconvert_kernel(const float* __restrict__ src,
                                __half* __restrict__ dh, int R, int C) {
    int e = blockIdx.z;
    int c0 = blockIdx.x * 32, r0 = blockIdx.y * 32;
    __shared__ float t[32][33];
    int tx = threadIdx.x & 31, ty = threadIdx.x >> 5;
    const float* s = src + (size_t)e * R * C;
    #pragma unroll
    for (int i = 0; i < 4; i++)
        t[ty + i * 8][tx] = s[(size_t)(r0 + ty + i * 8) * C + c0 + tx];
    __syncthreads();
    size_t ob = (size_t)e * C * R;
    #pragma unroll
    for (int i = 0; i < 4; i++) {
        int c = c0 + ty + i * 8;
        float v = t[tx][ty + i * 8];
        dh[ob + (size_t)c * R + r0 + tx] = __float2half_rn(v);
    }
}

// ---------------- gather: tokens -> fp16 plane ----------------
__global__ void gather_kernel(const float* __restrict__ x, __half* __restrict__ Ah) {
    int gid = blockIdx.x * 256 + threadIdx.x;
    int row = gid >> 7, j = gid & 127;
    int tok = g_rowidx[row];
    float4 v = make_float4(0, 0, 0, 0);
    if (tok >= 0) v = ((const float4*)(x + (size_t)tok * DMODEL))[j];
    uint2 ph = make_uint2(pack_h2(__float2half_rn(v.x), __float2half_rn(v.y)),
                          pack_h2(__float2half_rn(v.z), __float2half_rn(v.w)));
    ((uint2*)(Ah + (size_t)row * DMODEL))[j] = ph;
}

// ---------------- fp16 mma.sync GEMM: tile 128x128, K-stage 32, 4-stage, 2 CTAs/SM ----------------
#define RSTR 80
#define A_PL (128 * RSTR)          // 10240
#define B_PL (128 * RSTR)          // 10240
#define ST_A  0
#define ST_B  (A_PL)
#define ST_SZ (A_PL + B_PL)        // 20480
#define NST 4
#define SMEM_TOT (NST * ST_SZ)     // 81920  (x2 CTAs = 163840 <= 228KB)

template<int KTOT, int NF, bool G1>
__global__ void __launch_bounds__(256, 2)
gemm_mma(const __half* __restrict__ Ah, const __half* __restrict__ Bh,
         const float* __restrict__ bias,
         __half* __restrict__ Oh, float* __restrict__ Of, int cap, int tpe) {
    int e = blockIdx.y / tpe, mt = blockIdx.y % tpe;
    if (mt * 128 >= g_cnt[e]) return;
    const int row0 = mt * 128;
    const int n0 = blockIdx.x * 128;
    extern __shared__ char sm[];
    const uint32_t sb = s2u(sm);
    const int tid = threadIdx.x;
    const int wid = tid >> 5, lane = tid & 31;
    const int wm = wid >> 2, wn = wid & 3;    // warp tile 64x32: rows wm*64, cols wn*32

    const size_t arow0 = (size_t)e * cap + row0;
    const __half* pA = Ah + arow0 * KTOT;
    const __half* pB = Bh + ((size_t)e * NF + n0) * KTOT;

    auto load_stage = [&](int buf, int kbase) {
        uint32_t sbase = sb + buf * ST_SZ;
        #pragma unroll
        for (int j = 0; j < 2; j++) {               // A: 512 16B-chunks
            int idx = j * 256 + tid;
            int r = idx >> 2, c = idx & 3;
            cp16(sbase + ST_A + r * RSTR + c * 16, pA + (size_t)r * KTOT + kbase + c * 8);
        }
        #pragma unroll
        for (int j = 0; j < 2; j++) {               // B: 512 16B-chunks
            int idx = j * 256 + tid;
            int r = idx >> 2, c = idx & 3;
            cp16(sbase + ST_B + r * RSTR + c * 16, pB + (size_t)r * KTOT + kbase + c * 8);
        }
    };

    float acc[4][4][4];
    #pragma unroll
    for (int i = 0; i < 4; i++)
        #pragma unroll
        for (int j = 0; j < 4; j++)
            #pragma unroll
            for (int q = 0; q < 4; q++) acc[i][j][q] = 0.f;

    const uint32_t aAddr = (uint32_t)(wm * 64 + (lane & 15)) * RSTR + (lane >> 4) * 16;
    const uint32_t bAddr = (uint32_t)(wn * 32 + ((lane >> 4) & 1) * 8 + (lane & 7)) * RSTR
                           + ((lane >> 3) & 1) * 16;

    const int NK = KTOT / 32;
    load_stage(0, 0);  cp_commit();
    load_stage(1, 32); cp_commit();
    load_stage(2, 64); cp_commit();

    for (int s = 0; s < NK; s++) {
        cp_wait<2>();
        __syncthreads();

        uint32_t sbase = sb + (s % NST) * ST_SZ;
        #pragma unroll
        for (int kk = 0; kk < 2; kk++) {
            uint32_t koff = kk * 32;
            uint32_t ah[4][4], bh[2][4];
            #pragma unroll
            for (int mi = 0; mi < 4; mi++)
                ldm_x4(ah[mi], sbase + ST_A + aAddr + mi * (16 * RSTR) + koff);
            #pragma unroll
            for (int nq = 0; nq < 2; nq++)
                ldm_x4(bh[nq], sbase + ST_B + bAddr + nq * (16 * RSTR) + koff);
            #pragma unroll
            for (int mi = 0; mi < 4; mi++)
                #pragma unroll
                for (int nq = 0; nq < 2; nq++) {
                    mma16816(acc[mi][2 * nq],     ah[mi], bh[nq]);
                    mma16816(acc[mi][2 * nq + 1], ah[mi], bh[nq] + 2);
                }
        }

        if (s + 3 < NK) load_stage((s + 3) % NST, (s + 3) * 32);
        cp_commit();
    }

    // ---------------- epilogue (G1 direct stores; G2 fused combine via v2 reductions) ----------------
    const int colbase = n0 + wn * 32 + (lane & 3) * 2;
    const int rowbase = wm * 64 + (lane >> 2);
    float2 bvv[4];
    #pragma unroll
    for (int ni = 0; ni < 4; ni++)
        bvv[ni] = *(const float2*)(bias + (size_t)e * NF + colbase + ni * 8);
    #pragma unroll
    for (int mi = 0; mi < 4; mi++) {
        #pragma unroll
        for (int half = 0; half < 2; half++) {
            int r = rowbase + mi * 16 + half * 8;
            size_t grow = arow0 + r;
            if (G1) {
                #pragma unroll
                for (int ni = 0; ni < 4; ni++) {
                    int col = colbase + ni * 8;
                    float g0 = gelu_exact(acc[mi][ni][half * 2 + 0] + bvv[ni].x);
                    float g1 = gelu_exact(acc[mi][ni][half * 2 + 1] + bvv[ni].y);
                    *(uint32_t*)(Oh + grow * NF + col) =
                        pack_h2(__float2half_rn(g0), __float2half_rn(g1));
                }
            } else {
                int tok = g_rowidx[grow];
                if (tok >= 0) {
                    float w = g_wn[grow];
                    float* op = Of + (size_t)tok * DMODEL;
                    #pragma unroll
                    for (int ni = 0; ni < 4; ni++) {
                        int col = colbase + ni * 8;
                        float v0 = w * (acc[mi][ni][half * 2 + 0] + bvv[ni].x);
                        float v1 = w * (acc[mi][ni][half * 2 + 1] + bvv[ni].y);
                        red_v2(op + col, v0, v1);
                    }
                }
            }
        }
    }
}

// ---------------- launch ----------------
extern "C" void kernel_launch(void* const* d_in, const int* in_sizes, int n_in,
                              void* d_out, int out_size) {
    const float* x  = (const float*)d_in[0];
    const float* Wr = (const float*)d_in[1];
    const float* br = (const float*)d_in[2];
    const float* W1 = (const float*)d_in[3];
    const float* b1 = (const float*)d_in[4];
    const float* W2 = (const float*)d_in[5];
    const float* b2 = (const float*)d_in[6];
    float* out = (float*)d_out;

    int N = in_sizes[0] / DMODEL;
    if (N > NMAX) N = NMAX;
    int cap = (5 * N + 15) / 16;
    if (cap > CAPMAX) cap = CAPMAX;
    int tpe = (cap + 127) / 128;
    int nblk = (N + 255) / 256;

    void *a1h, *hh, *w1h, *w2h, *ridx;
    cudaGetSymbolAddress(&a1h, g_A1h);
    cudaGetSymbolAddress(&hh,  g_Hh);
    cudaGetSymbolAddress(&w1h, g_W1h); cudaGetSymbolAddress(&w2h, g_W2h);
    cudaGetSymbolAddress(&ridx, g_rowidx);

    cudaFuncSetAttribute(gemm_mma<DMODEL, DFF, true>,
                         cudaFuncAttributeMaxDynamicSharedMemorySize, SMEM_TOT);
    cudaFuncSetAttribute(gemm_mma<DFF, DMODEL, false>,
                         cudaFuncAttributeMaxDynamicSharedMemorySize, SMEM_TOT);

    // side stream for weight conversion (event fork/join: graph-capture safe)
    cudaStream_t s2;
    cudaStreamCreateWithFlags(&s2, cudaStreamNonBlocking);
    cudaEvent_t ev0, ev1;
    cudaEventCreateWithFlags(&ev0, cudaEventDisableTiming);
    cudaEventCreateWithFlags(&ev1, cudaEventDisableTiming);

    cudaMemsetAsync(out, 0, (size_t)out_size * sizeof(float));
    cudaMemsetAsync(ridx, 0xFF, (size_t)EROWS * sizeof(int));   // all slots -> -1
    cudaEventRecord(ev0, 0);
    cudaStreamWaitEvent(s2, ev0, 0);
    wconvert_kernel<<<dim3(DFF / 32, DMODEL / 32, NEXP), 256, 0, s2>>>(
        W1, (__half*)w1h, DMODEL, DFF);
    wconvert_kernel<<<dim3(DMODEL / 32, DFF / 32, NEXP), 256, 0, s2>>>(
        W2, (__half*)w2h, DFF, DMODEL);
    cudaEventRecord(ev1, s2);

    router_kernel<<<(N * 32 + 255) / 256, 256>>>(x, Wr, br, N);
    count_kernel<<<nblk, 256>>>(N);
    scan_kernel<<<1, NB>>>(cap);
    scatter_kernel<<<nblk, 256>>>(N, cap);
    gather_kernel<<<(NEXP * cap * 128) / 256, 256>>>(x, (__half*)a1h);

    cudaStreamWaitEvent(0, ev1, 0);

    dim3 g1(DFF / 128, NEXP * tpe);
    gemm_mma<DMODEL, DFF, true><<<g1, 256, SMEM_TOT>>>(
        (const __half*)a1h, (const __half*)w1h, b1,
        (__half*)hh, nullptr, cap, tpe);

    dim3 g2(DMODEL / 128, NEXP * tpe);
    gemm_mma<DFF, DMODEL, false><<<g2, 256, SMEM_TOT>>>(
        (const __half*)hh, (const __half*)w2h, b2,
        nullptr, out, cap, tpe);
}

// round 14
// speedup vs baseline: 1.4430x; 1.0585x over previous
#include <cuda_runtime.h>
#include <cuda_fp16.h>
#include <cstdint>

#define DMODEL 512
#define DFF 2048
#define NEXP 8
#define TOPK 2
#define NMAX 32768
#define CAPMAX 10240
#define EROWS (NEXP * CAPMAX)
#define NB 128                 // dispatch blocks (N/256)

typedef unsigned long long ull;

// ---------------- scratch ----------------
__device__ __align__(1024) __half g_A1h[(size_t)EROWS * DMODEL];
__device__ __align__(1024) __half g_Hh [(size_t)EROWS * DFF];
__device__ __align__(1024) __half g_W1h[(size_t)NEXP * DFF * DMODEL];   // [e][n][k]
__device__ __align__(1024) __half g_W2h[(size_t)NEXP * DMODEL * DFF];   // [e][n][k]
__device__ int    g_rowidx[EROWS];     // slot -> token (-1 pad)
__device__ float  g_wn[EROWS];         // slot -> normalized combine weight
__device__ int2   g_ti[NMAX];
__device__ float2 g_tw[NMAX];
__device__ int    g_cnt[NEXP];
__device__ int    g_blkcnt[NB * NEXP];
__device__ int    g_blkoff[NB * NEXP];

// ---------------- helpers ----------------
__device__ __forceinline__ uint32_t s2u(const void* p) {
    uint32_t a;
    asm("{ .reg .u64 t; cvta.to.shared.u64 t, %1; cvt.u32.u64 %0, t; }" : "=r"(a) : "l"(p));
    return a;
}
__device__ __forceinline__ float gelu_exact(float v) {
    return 0.5f * v * (1.0f + erff(v * 0.7071067811865476f));
}
__device__ __forceinline__ uint32_t pack_h2(__half a, __half b) {
    return (uint32_t)__half_as_ushort(a) | ((uint32_t)__half_as_ushort(b) << 16);
}

__device__ __forceinline__ void cp16(uint32_t s, const void* g) {
    asm volatile("cp.async.cg.shared.global [%0], [%1], 16;" :: "r"(s), "l"(g));
}
__device__ __forceinline__ void cp_commit() { asm volatile("cp.async.commit_group;"); }
template<int N> __device__ __forceinline__ void cp_wait() {
    asm volatile("cp.async.wait_group %0;" :: "n"(N));
}
__device__ __forceinline__ void ldm_x4(uint32_t* r, uint32_t a) {
    asm volatile("ldmatrix.sync.aligned.m8n8.x4.shared.b16 {%0,%1,%2,%3}, [%4];"
                 : "=r"(r[0]), "=r"(r[1]), "=r"(r[2]), "=r"(r[3]) : "r"(a));
}
__device__ __forceinline__ void mma16816(float* c, const uint32_t* a, const uint32_t* b) {
    asm volatile(
        "mma.sync.aligned.m16n8k16.row.col.f32.f16.f16.f32 "
        "{%0,%1,%2,%3}, {%4,%5,%6,%7}, {%8,%9}, {%0,%1,%2,%3};"
        : "+f"(c[0]), "+f"(c[1]), "+f"(c[2]), "+f"(c[3])
        : "r"(a[0]), "r"(a[1]), "r"(a[2]), "r"(a[3]), "r"(b[0]), "r"(b[1]));
}
__device__ __forceinline__ void red_v2(float* addr, float v0, float v1) {
    asm volatile("red.global.add.v2.f32 [%0], {%1, %2};"
                 :: "l"(addr), "f"(v0), "f"(v1) : "memory");
}

// ---------------- router ----------------
__global__ void router_kernel(const float* __restrict__ x,
                              const float* __restrict__ Wr,
                              const float* __restrict__ br, int N) {
    int warp = (blockIdx.x * blockDim.x + threadIdx.x) >> 5;
    int lane = threadIdx.x & 31;
    if (warp >= N) return;
    const float* xr = x + (size_t)warp * DMODEL;
    float acc[8] = {0, 0, 0, 0, 0, 0, 0, 0};
    for (int d = lane; d < DMODEL; d += 32) {
        float xv = xr[d];
        float4 w0 = *(const float4*)(Wr + (size_t)d * 8);
        float4 w1 = *(const float4*)(Wr + (size_t)d * 8 + 4);
        acc[0] += xv * w0.x; acc[1] += xv * w0.y;
        acc[2] += xv * w0.z; acc[3] += xv * w0.w;
        acc[4] += xv * w1.x; acc[5] += xv * w1.y;
        acc[6] += xv * w1.z; acc[7] += xv * w1.w;
    }
    #pragma unroll
    for (int o = 16; o; o >>= 1)
        #pragma unroll
        for (int e = 0; e < 8; e++)
            acc[e] += __shfl_xor_sync(0xFFFFFFFFu, acc[e], o);
    if (lane == 0) {
        float l[8], p[8];
        float m = -1e30f;
        #pragma unroll
        for (int e = 0; e < 8; e++) { l[e] = acc[e] + br[e]; m = fmaxf(m, l[e]); }
        float s = 0.f;
        #pragma unroll
        for (int e = 0; e < 8; e++) { p[e] = expf(l[e] - m); s += p[e]; }
        float inv = 1.0f / s;
        #pragma unroll
        for (int e = 0; e < 8; e++) p[e] *= inv;
        int i1 = 0; float p1 = p[0];
        #pragma unroll
        for (int e = 1; e < 8; e++) if (p[e] > p1) { p1 = p[e]; i1 = e; }
        int i2 = -1; float p2 = -1.0f;
        #pragma unroll
        for (int e = 0; e < 8; e++) if (e != i1 && p[e] > p2) { p2 = p[e]; i2 = e; }
        float den = p1 + p2 + 1e-9f;
        g_ti[warp] = make_int2(i1, i2);
        g_tw[warp] = make_float2(p1 / den, p2 / den);
    }
}

// ---------------- dispatch phase 1: per-block expert histograms ----------------
__global__ void count_kernel(int N) {
    __shared__ int sc[8];
    int t = threadIdx.x, b = blockIdx.x;
    if (t < 8) sc[t] = 0;
    __syncthreads();
    int tok = b * 256 + t;
    if (tok < N) {
        int2 ti = g_ti[tok];
        atomicAdd(&sc[ti.x], 1);
        atomicAdd(&sc[ti.y], 1);
    }
    __syncthreads();
    if (t < 8) g_blkcnt[b * 8 + t] = sc[t];
}

// ---------------- dispatch phase 2: scan block histograms ----------------
__global__ void scan_kernel(int cap) {      // 1 block, NB threads
    __shared__ int sm[NB][8];
    int t = threadIdx.x;
    int own[8], v[8];
    #pragma unroll
    for (int e = 0; e < 8; e++) { own[e] = g_blkcnt[t * 8 + e]; v[e] = own[e]; sm[t][e] = own[e]; }
    __syncthreads();
    #pragma unroll
    for (int off = 1; off < NB; off <<= 1) {
        int u[8] = {0, 0, 0, 0, 0, 0, 0, 0};
        if (t >= off) {
            #pragma unroll
            for (int e = 0; e < 8; e++) u[e] = sm[t - off][e];
        }
        __syncthreads();
        #pragma unroll
        for (int e = 0; e < 8; e++) { v[e] += u[e]; sm[t][e] = v[e]; }
        __syncthreads();
    }
    #pragma unroll
    for (int e = 0; e < 8; e++) g_blkoff[t * 8 + e] = v[e] - own[e];
    if (t == NB - 1) {
        #pragma unroll
        for (int e = 0; e < 8; e++) g_cnt[e] = min(v[e], cap);
    }
}

// ---------------- dispatch phase 3: scatter slots (thread = token, order preserved) ----------------
__global__ void scatter_kernel(int N, int cap) {
    __shared__ int sm[256][8];
    int t = threadIdx.x, b = blockIdx.x;
    int tok = b * 256 + t;
    int2 ti = make_int2(0, 0);
    float2 tw = make_float2(0.f, 0.f);
    int cnt[8] = {0, 0, 0, 0, 0, 0, 0, 0};
    bool valid = tok < N;
    if (valid) {
        ti = g_ti[tok]; tw = g_tw[tok];
        cnt[ti.x]++; cnt[ti.y]++;
    }
    int v[8];
    #pragma unroll
    for (int e = 0; e < 8; e++) { v[e] = cnt[e]; sm[t][e] = cnt[e]; }
    __syncthreads();
    #pragma unroll
    for (int off = 1; off < 256; off <<= 1) {
        int u[8] = {0, 0, 0, 0, 0, 0, 0, 0};
        if (t >= off) {
            #pragma unroll
            for (int e = 0; e < 8; e++) u[e] = sm[t - off][e];
        }
        __syncthreads();
        #pragma unroll
        for (int e = 0; e < 8; e++) { v[e] += u[e]; sm[t][e] = v[e]; }
        __syncthreads();
    }
    if (valid) {
        int p0 = v[ti.x] - cnt[ti.x] + g_blkoff[b * 8 + ti.x];
        int p1 = v[ti.y] - cnt[ti.y] + g_blkoff[b * 8 + ti.y];
        bool k0 = p0 < cap, k1 = p1 < cap;
        float w0 = k0 ? tw.x : 0.0f;
        float w1 = k1 ? tw.y : 0.0f;
        float inv = 1.0f / (w0 + w1 + 1e-9f);
        if (k0) {
            int sl = ti.x * cap + p0;
            g_rowidx[sl] = tok; g_wn[sl] = w0 * inv;
        }
        if (k1) {
            int sl = ti.y * cap + p1;
            g_rowidx[sl] = tok; g_wn[sl] = w1 * inv;
        }
    }
}

// ---------------- weight convert+transpose: [e][R][C] f32 -> [e][C][R] fp16 ----------------
__global__ void wconvert_kernel(const float* __restrict__ src,
                                __half* __restrict__ dh, int R, int C) {
    int e = blockIdx.z;
    int c0 = blockIdx.x * 32, r0 = blockIdx.y * 32;
    __shared__ float t[32][33];
    int tx = threadIdx.x & 31, ty = threadIdx.x >> 5;
    const float* s = src + (size_t)e * R * C;
    #pragma unroll
    for (int i = 0; i < 4; i++)
        t[ty + i * 8][tx] = s[(size_t)(r0 + ty + i * 8) * C + c0 + tx];
    __syncthreads();
    size_t ob = (size_t)e * C * R;
    #pragma unroll
    for (int i = 0; i < 4; i++) {
        int c = c0 + ty + i * 8;
        float v = t[tx][ty + i * 8];
        dh[ob + (size_t)c * R + r0 + tx] = __float2half_rn(v);
    }
}

// ---------------- gather: tokens -> fp16 plane ----------------
__global__ void gather_kernel(const float* __restrict__ x, __half* __restrict__ Ah) {
    int gid = blockIdx.x * 256 + threadIdx.x;
    int row = gid >> 7, j = gid & 127;
    int tok = g_rowidx[row];
    float4 v = make_float4(0, 0, 0, 0);
    if (tok >= 0) v = ((const float4*)(x + (size_t)tok * DMODEL))[j];
    uint2 ph = make_uint2(pack_h2(__float2half_rn(v.x), __float2half_rn(v.y)),
                          pack_h2(__float2half_rn(v.z), __float2half_rn(v.w)));
    ((uint2*)(Ah + (size_t)row * DMODEL))[j] = ph;
}

// ---------------- fp16 mma.sync GEMM: tile 128x128, K-stage 32, 5-stage, 2 CTAs/SM ----------------
#define RSTR 80
#define A_PL (128 * RSTR)          // 10240
#define B_PL (128 * RSTR)          // 10240
#define ST_A  0
#define ST_B  (A_PL)
#define ST_SZ (A_PL + B_PL)        // 20480
#define NST 5
#define SMEM_TOT (NST * ST_SZ)     // 102400  (x2 CTAs = 204800 <= 228KB)

template<int KTOT, int NF, bool G1>
__global__ void __launch_bounds__(256, 2)
gemm_mma(const __half* __restrict__ Ah, const __half* __restrict__ Bh,
         const float* __restrict__ bias,
         __half* __restrict__ Oh, float* __restrict__ Of, int cap, int tpe) {
    int e = blockIdx.y / tpe, mt = blockIdx.y % tpe;
    if (mt * 128 >= g_cnt[e]) return;
    const int row0 = mt * 128;
    const int n0 = blockIdx.x * 128;
    extern __shared__ char sm[];
    const uint32_t sb = s2u(sm);
    const int tid = threadIdx.x;
    const int wid = tid >> 5, lane = tid & 31;
    const int wm = wid >> 2, wn = wid & 3;    // warp tile 64x32

    const size_t arow0 = (size_t)e * cap + row0;
    const __half* pA = Ah + arow0 * KTOT;
    const __half* pB = Bh + ((size_t)e * NF + n0) * KTOT;

    auto load_stage = [&](int buf, int kbase) {
        uint32_t sbase = sb + buf * ST_SZ;
        #pragma unroll
        for (int j = 0; j < 2; j++) {               // A: 512 16B-chunks
            int idx = j * 256 + tid;
            int r = idx >> 2, c = idx & 3;
            cp16(sbase + ST_A + r * RSTR + c * 16, pA + (size_t)r * KTOT + kbase + c * 8);
        }
        #pragma unroll
        for (int j = 0; j < 2; j++) {               // B: 512 16B-chunks
            int idx = j * 256 + tid;
            int r = idx >> 2, c = idx & 3;
            cp16(sbase + ST_B + r * RSTR + c * 16, pB + (size_t)r * KTOT + kbase + c * 8);
        }
    };

    float acc[4][4][4];
    #pragma unroll
    for (int i = 0; i < 4; i++)
        #pragma unroll
        for (int j = 0; j < 4; j++)
            #pragma unroll
            for (int q = 0; q < 4; q++) acc[i][j][q] = 0.f;

    const uint32_t aAddr = (uint32_t)(wm * 64 + (lane & 15)) * RSTR + (lane >> 4) * 16;
    const uint32_t bAddr = (uint32_t)(wn * 32 + ((lane >> 4) & 1) * 8 + (lane & 7)) * RSTR
                           + ((lane >> 3) & 1) * 16;

    const int NK = KTOT / 32;
    load_stage(0, 0);  cp_commit();
    load_stage(1, 32); cp_commit();
    load_stage(2, 64); cp_commit();
    load_stage(3, 96); cp_commit();

    for (int s = 0; s < NK; s++) {
        cp_wait<3>();
        __syncthreads();

        uint32_t sbase = sb + (s % NST) * ST_SZ;
        #pragma unroll
        for (int kk = 0; kk < 2; kk++) {
            uint32_t koff = kk * 32;
            uint32_t ah[4][4], bh[2][4];
            #pragma unroll
            for (int mi = 0; mi < 4; mi++)
                ldm_x4(ah[mi], sbase + ST_A + aAddr + mi * (16 * RSTR) + koff);
            #pragma unroll
            for (int nq = 0; nq < 2; nq++)
                ldm_x4(bh[nq], sbase + ST_B + bAddr + nq * (16 * RSTR) + koff);
            #pragma unroll
            for (int mi = 0; mi < 4; mi++)
                #pragma unroll
                for (int nq = 0; nq < 2; nq++) {
                    mma16816(acc[mi][2 * nq],     ah[mi], bh[nq]);
                    mma16816(acc[mi][2 * nq + 1], ah[mi], bh[nq] + 2);
                }
        }

        if (s + 4 < NK) load_stage((s + 4) % NST, (s + 4) * 32);
        cp_commit();
    }

    // ---------------- epilogue (G1 direct stores; G2 fused combine via v2 reductions) ----------------
    const int colbase = n0 + wn * 32 + (lane & 3) * 2;
    const int rowbase = wm * 64 + (lane >> 2);
    float2 bvv[4];
    #pragma unroll
    for (int ni = 0; ni < 4; ni++)
        bvv[ni] = *(const float2*)(bias + (size_t)e * NF + colbase + ni * 8);
    #pragma unroll
    for (int mi = 0; mi < 4; mi++) {
        #pragma unroll
        for (int half = 0; half < 2; half++) {
            int r = rowbase + mi * 16 + half * 8;
            size_t grow = arow0 + r;
            if (G1) {
                #pragma unroll
                for (int ni = 0; ni < 4; ni++) {
                    int col = colbase + ni * 8;
                    float g0 = gelu_exact(acc[mi][ni][half * 2 + 0] + bvv[ni].x);
                    float g1 = gelu_exact(acc[mi][ni][half * 2 + 1] + bvv[ni].y);
                    *(uint32_t*)(Oh + grow * NF + col) =
                        pack_h2(__float2half_rn(g0), __float2half_rn(g1));
                }
            } else {
                int tok = g_rowidx[grow];
                if (tok >= 0) {
                    float w = g_wn[grow];
                    float* op = Of + (size_t)tok * DMODEL;
                    #pragma unroll
                    for (int ni = 0; ni < 4; ni++) {
                        int col = colbase + ni * 8;
                        float v0 = w * (acc[mi][ni][half * 2 + 0] + bvv[ni].x);
                        float v1 = w * (acc[mi][ni][half * 2 + 1] + bvv[ni].y);
                        red_v2(op + col, v0, v1);
                    }
                }
            }
        }
    }
}

// ---------------- launch ----------------
extern "C" void kernel_launch(void* const* d_in, const int* in_sizes, int n_in,
                              void* d_out, int out_size) {
    const float* x  = (const float*)d_in[0];
    const float* Wr = (const float*)d_in[1];
    const float* br = (const float*)d_in[2];
    const float* W1 = (const float*)d_in[3];
    const float* b1 = (const float*)d_in[4];
    const float* W2 = (const float*)d_in[5];
    const float* b2 = (const float*)d_in[6];
    float* out = (float*)d_out;

    int N = in_sizes[0] / DMODEL;
    if (N > NMAX) N = NMAX;
    int cap = (5 * N + 15) / 16;
    if (cap > CAPMAX) cap = CAPMAX;
    int tpe = (cap + 127) / 128;
    int nblk = (N + 255) / 256;

    void *a1h, *hh, *w1h, *w2h, *ridx;
    cudaGetSymbolAddress(&a1h, g_A1h);
    cudaGetSymbolAddress(&hh,  g_Hh);
    cudaGetSymbolAddress(&w1h, g_W1h); cudaGetSymbolAddress(&w2h, g_W2h);
    cudaGetSymbolAddress(&ridx, g_rowidx);

    cudaFuncSetAttribute(gemm_mma<DMODEL, DFF, true>,
                         cudaFuncAttributeMaxDynamicSharedMemorySize, SMEM_TOT);
    cudaFuncSetAttribute(gemm_mma<DFF, DMODEL, false>,
                         cudaFuncAttributeMaxDynamicSharedMemorySize, SMEM_TOT);

    // side stream for weight conversion (event fork/join: graph-capture safe)
    cudaStream_t s2;
    cudaStreamCreateWithFlags(&s2, cudaStreamNonBlocking);
    cudaEvent_t ev0, ev1;
    cudaEventCreateWithFlags(&ev0, cudaEventDisableTiming);
    cudaEventCreateWithFlags(&ev1, cudaEventDisableTiming);

    cudaMemsetAsync(out, 0, (size_t)out_size * sizeof(float));
    cudaMemsetAsync(ridx, 0xFF, (size_t)EROWS * sizeof(int));   // all slots -> -1
    cudaEventRecord(ev0, 0);
    cudaStreamWaitEvent(s2, ev0, 0);
    wconvert_kernel<<<dim3(DFF / 32, DMODEL / 32, NEXP), 256, 0, s2>>>(
        W1, (__half*)w1h, DMODEL, DFF);
    wconvert_kernel<<<dim3(DMODEL / 32, DFF / 32, NEXP), 256, 0, s2>>>(
        W2, (__half*)w2h, DFF, DMODEL);
    cudaEventRecord(ev1, s2);

    router_kernel<<<(N * 32 + 255) / 256, 256>>>(x, Wr, br, N);
    count_kernel<<<nblk, 256>>>(N);
    scan_kernel<<<1, NB>>>(cap);
    scatter_kernel<<<nblk, 256>>>(N, cap);
    gather_kernel<<<(NEXP * cap * 128) / 256, 256>>>(x, (__half*)a1h);

    cudaStreamWaitEvent(0, ev1, 0);

    dim3 g1(DFF / 128, NEXP * tpe);
    gemm_mma<DMODEL, DFF, true><<<g1, 256, SMEM_TOT>>>(
        (const __half*)a1h, (const __half*)w1h, b1,
        (__half*)hh, nullptr, cap, tpe);

    dim3 g2(DMODEL / 128, NEXP * tpe);
    gemm_mma<DFF, DMODEL, false><<<g2, 256, SMEM_TOT>>>(
        (const __half*)hh, (const __half*)w2h, b2,
        nullptr, out, cap, tpe);
}

// round 16
// speedup vs baseline: 1.4982x; 1.0383x over previous
#include <cuda_runtime.h>
#include <cuda_fp16.h>
#include <cstdint>

#define DMODEL 512
#define DFF 2048
#define NEXP 8
#define TOPK 2
#define NMAX 32768
#define CAPMAX 10240
#define EROWS (NEXP * CAPMAX)
#define NB 128                 // dispatch blocks (N/256)

typedef unsigned long long ull;

// ---------------- scratch ----------------
__device__ __align__(1024) __half g_X16[(size_t)NMAX * DMODEL];          // fp16 tokens
__device__ __align__(1024) __half g_Hh [(size_t)EROWS * DFF];
__device__ __align__(1024) __half g_W1h[(size_t)NEXP * DFF * DMODEL];   // [e][n][k]
__device__ __align__(1024) __half g_W2h[(size_t)NEXP * DMODEL * DFF];   // [e][n][k]
__device__ int    g_rowidx[EROWS];     // slot -> token (-1 pad)
__device__ float  g_wn[EROWS];         // slot -> normalized combine weight
__device__ int2   g_ti[NMAX];
__device__ float2 g_tw[NMAX];
__device__ int    g_cnt[NEXP];
__device__ int    g_blkcnt[NB * NEXP];
__device__ int    g_blkoff[NB * NEXP];

// ---------------- helpers ----------------
__device__ __forceinline__ uint32_t s2u(const void* p) {
    uint32_t a;
    asm("{ .reg .u64 t; cvta.to.shared.u64 t, %1; cvt.u32.u64 %0, t; }" : "=r"(a) : "l"(p));
    return a;
}
__device__ __forceinline__ float gelu_exact(float v) {
    return 0.5f * v * (1.0f + erff(v * 0.7071067811865476f));
}
__device__ __forceinline__ uint32_t pack_h2(__half a, __half b) {
    return (uint32_t)__half_as_ushort(a) | ((uint32_t)__half_as_ushort(b) << 16);
}

__device__ __forceinline__ void cp16(uint32_t s, const void* g) {
    asm volatile("cp.async.cg.shared.global [%0], [%1], 16;" :: "r"(s), "l"(g));
}
__device__ __forceinline__ void cp_commit() { asm volatile("cp.async.commit_group;"); }
template<int N> __device__ __forceinline__ void cp_wait() {
    asm volatile("cp.async.wait_group %0;" :: "n"(N));
}
__device__ __forceinline__ void ldm_x4(uint32_t* r, uint32_t a) {
    asm volatile("ldmatrix.sync.aligned.m8n8.x4.shared.b16 {%0,%1,%2,%3}, [%4];"
                 : "=r"(r[0]), "=r"(r[1]), "=r"(r[2]), "=r"(r[3]) : "r"(a));
}
__device__ __forceinline__ void mma16816(float* c, const uint32_t* a, const uint32_t* b) {
    asm volatile(
        "mma.sync.aligned.m16n8k16.row.col.f32.f16.f16.f32 "
        "{%0,%1,%2,%3}, {%4,%5,%6,%7}, {%8,%9}, {%0,%1,%2,%3};"
        : "+f"(c[0]), "+f"(c[1]), "+f"(c[2]), "+f"(c[3])
        : "r"(a[0]), "r"(a[1]), "r"(a[2]), "r"(a[3]), "r"(b[0]), "r"(b[1]));
}
__device__ __forceinline__ void red_v2(float* addr, float v0, float v1) {
    asm volatile("red.global.add.v2.f32 [%0], {%1, %2};"
                 :: "l"(addr), "f"(v0), "f"(v1) : "memory");
}

// ---------------- router (+ fp16 conversion of x) ----------------
__global__ void router_kernel(const float* __restrict__ x,
                              const float* __restrict__ Wr,
                              const float* __restrict__ br,
                              __half* __restrict__ x16, int N) {
    int warp = (blockIdx.x * blockDim.x + threadIdx.x) >> 5;
    int lane = threadIdx.x & 31;
    if (warp >= N) return;
    const float* xr = x + (size_t)warp * DMODEL;
    __half* xo = x16 + (size_t)warp * DMODEL;
    float acc[8] = {0, 0, 0, 0, 0, 0, 0, 0};
    for (int d = lane; d < DMODEL; d += 32) {
        float xv = xr[d];
        xo[d] = __float2half_rn(xv);
        float4 w0 = *(const float4*)(Wr + (size_t)d * 8);
        float4 w1 = *(const float4*)(Wr + (size_t)d * 8 + 4);
        acc[0] += xv * w0.x; acc[1] += xv * w0.y;
        acc[2] += xv * w0.z; acc[3] += xv * w0.w;
        acc[4] += xv * w1.x; acc[5] += xv * w1.y;
        acc[6] += xv * w1.z; acc[7] += xv * w1.w;
    }
    #pragma unroll
    for (int o = 16; o; o >>= 1)
        #pragma unroll
        for (int e = 0; e < 8; e++)
            acc[e] += __shfl_xor_sync(0xFFFFFFFFu, acc[e], o);
    if (lane == 0) {
        float l[8], p[8];
        float m = -1e30f;
        #pragma unroll
        for (int e = 0; e < 8; e++) { l[e] = acc[e] + br[e]; m = fmaxf(m, l[e]); }
        float s = 0.f;
        #pragma unroll
        for (int e = 0; e < 8; e++) { p[e] = expf(l[e] - m); s += p[e]; }
        float inv = 1.0f / s;
        #pragma unroll
        for (int e = 0; e < 8; e++) p[e] *= inv;
        int i1 = 0; float p1 = p[0];
        #pragma unroll
        for (int e = 1; e < 8; e++) if (p[e] > p1) { p1 = p[e]; i1 = e; }
        int i2 = -1; float p2 = -1.0f;
        #pragma unroll
        for (int e = 0; e < 8; e++) if (e != i1 && p[e] > p2) { p2 = p[e]; i2 = e; }
        float den = p1 + p2 + 1e-9f;
        g_ti[warp] = make_int2(i1, i2);
        g_tw[warp] = make_float2(p1 / den, p2 / den);
    }
}

// ---------------- dispatch phase 1: per-block expert histograms ----------------
__global__ void count_kernel(int N) {
    __shared__ int sc[8];
    int t = threadIdx.x, b = blockIdx.x;
    if (t < 8) sc[t] = 0;
    __syncthreads();
    int tok = b * 256 + t;
    if (tok < N) {
        int2 ti = g_ti[tok];
        atomicAdd(&sc[ti.x], 1);
        atomicAdd(&sc[ti.y], 1);
    }
    __syncthreads();
    if (t < 8) g_blkcnt[b * 8 + t] = sc[t];
}

// ---------------- dispatch phase 2: scan block histograms ----------------
__global__ void scan_kernel(int cap) {      // 1 block, NB threads
    __shared__ int sm[NB][8];
    int t = threadIdx.x;
    int own[8], v[8];
    #pragma unroll
    for (int e = 0; e < 8; e++) { own[e] = g_blkcnt[t * 8 + e]; v[e] = own[e]; sm[t][e] = own[e]; }
    __syncthreads();
    #pragma unroll
    for (int off = 1; off < NB; off <<= 1) {
        int u[8] = {0, 0, 0, 0, 0, 0, 0, 0};
        if (t >= off) {
            #pragma unroll
            for (int e = 0; e < 8; e++) u[e] = sm[t - off][e];
        }
        __syncthreads();
        #pragma unroll
        for (int e = 0; e < 8; e++) { v[e] += u[e]; sm[t][e] = v[e]; }
        __syncthreads();
    }
    #pragma unroll
    for (int e = 0; e < 8; e++) g_blkoff[t * 8 + e] = v[e] - own[e];
    if (t == NB - 1) {
        #pragma unroll
        for (int e = 0; e < 8; e++) g_cnt[e] = min(v[e], cap);
    }
}

// ---------------- dispatch phase 3: scatter slots (thread = token, order preserved) ----------------
__global__ void scatter_kernel(int N, int cap) {
    __shared__ int sm[256][8];
    int t = threadIdx.x, b = blockIdx.x;
    int tok = b * 256 + t;
    int2 ti = make_int2(0, 0);
    float2 tw = make_float2(0.f, 0.f);
    int cnt[8] = {0, 0, 0, 0, 0, 0, 0, 0};
    bool valid = tok < N;
    if (valid) {
        ti = g_ti[tok]; tw = g_tw[tok];
        cnt[ti.x]++; cnt[ti.y]++;
    }
    int v[8];
    #pragma unroll
    for (int e = 0; e < 8; e++) { v[e] = cnt[e]; sm[t][e] = cnt[e]; }
    __syncthreads();
    #pragma unroll
    for (int off = 1; off < 256; off <<= 1) {
        int u[8] = {0, 0, 0, 0, 0, 0, 0, 0};
        if (t >= off) {
            #pragma unroll
            for (int e = 0; e < 8; e++) u[e] = sm[t - off][e];
        }
        __syncthreads();
        #pragma unroll
        for (int e = 0; e < 8; e++) { v[e] += u[e]; sm[t][e] = v[e]; }
        __syncthreads();
    }
    if (valid) {
        int p0 = v[ti.x] - cnt[ti.x] + g_blkoff[b * 8 + ti.x];
        int p1 = v[ti.y] - cnt[ti.y] + g_blkoff[b * 8 + ti.y];
        bool k0 = p0 < cap, k1 = p1 < cap;
        float w0 = k0 ? tw.x : 0.0f;
        float w1 = k1 ? tw.y : 0.0f;
        float inv = 1.0f / (w0 + w1 + 1e-9f);
        if (k0) {
            int sl = ti.x * cap + p0;
            g_rowidx[sl] = tok; g_wn[sl] = w0 * inv;
        }
        if (k1) {
            int sl = ti.y * cap + p1;
            g_rowidx[sl] = tok; g_wn[sl] = w1 * inv;
        }
    }
}

// ---------------- weight convert+transpose: [e][R][C] f32 -> [e][C][R] fp16 ----------------
__global__ void wconvert_kernel(const float* __restrict__ src,
                                __half* __restrict__ dh, int R, int C) {
    int e = blockIdx.z;
    int c0 = blockIdx.x * 32, r0 = blockIdx.y * 32;
    __shared__ float t[32][33];
    int tx = threadIdx.x & 31, ty = threadIdx.x >> 5;
    const float* s = src + (size_t)e * R * C;
    #pragma unroll
    for (int i = 0; i < 4; i++)
        t[ty + i * 8][tx] = s[(size_t)(r0 + ty + i * 8) * C + c0 + tx];
    __syncthreads();
    size_t ob = (size_t)e * C * R;
    #pragma unroll
    for (int i = 0; i < 4; i++) {
        int c = c0 + ty + i * 8;
        float v = t[tx][ty + i * 8];
        dh[ob + (size_t)c * R + r0 + tx] = __float2half_rn(v);
    }
}

// ---------------- fp16 mma.sync GEMM: tile 128x128, K-stage 32, 5-stage, 2 CTAs/SM ----------------
// G1 = true: A rows fetched directly from x16 via g_rowidx indirection.
#define RSTR 80
#define A_PL (128 * RSTR)          // 10240
#define B_PL (128 * RSTR)          // 10240
#define ST_A  0
#define ST_B  (A_PL)
#define ST_SZ (A_PL + B_PL)        // 20480
#define NST 5
#define SMEM_TOT (NST * ST_SZ)     // 102400  (x2 CTAs = 204800 <= 228KB)

template<int KTOT, int NF, bool G1>
__global__ void __launch_bounds__(256, 2)
gemm_mma(const __half* __restrict__ Ah, const __half* __restrict__ Bh,
         const float* __restrict__ bias,
         __half* __restrict__ Oh, float* __restrict__ Of, int cap, int tpe) {
    int e = blockIdx.y / tpe, mt = blockIdx.y % tpe;
    if (mt * 128 >= g_cnt[e]) return;
    const int row0 = mt * 128;
    const int n0 = blockIdx.x * 128;
    extern __shared__ char sm[];
    const uint32_t sb = s2u(sm);
    const int tid = threadIdx.x;
    const int wid = tid >> 5, lane = tid & 31;
    const int wm = wid >> 2, wn = wid & 3;    // warp tile 64x32

    const size_t arow0 = (size_t)e * cap + row0;
    const __half* pB = Bh + ((size_t)e * NF + n0) * KTOT;

    // A source pointers (per thread: 2 fixed rows across all stages)
    const int ar = tid >> 2, ac = tid & 3;
    const __half* pA0;
    const __half* pA1;
    if (G1) {
        int tok0 = g_rowidx[arow0 + ar];       if (tok0 < 0) tok0 = 0;
        int tok1 = g_rowidx[arow0 + 64 + ar];  if (tok1 < 0) tok1 = 0;
        pA0 = Ah + (size_t)tok0 * KTOT + ac * 8;
        pA1 = Ah + (size_t)tok1 * KTOT + ac * 8;
    } else {
        const __half* pA = Ah + arow0 * KTOT;
        pA0 = pA + (size_t)ar * KTOT + ac * 8;
        pA1 = pA + (size_t)(64 + ar) * KTOT + ac * 8;
    }
    const uint32_t sA0 = ar * RSTR + ac * 16;
    const uint32_t sA1 = (64 + ar) * RSTR + ac * 16;

    auto load_stage = [&](int buf, int kbase) {
        uint32_t sbase = sb + buf * ST_SZ;
        cp16(sbase + ST_A + sA0, pA0 + kbase);
        cp16(sbase + ST_A + sA1, pA1 + kbase);
        #pragma unroll
        for (int j = 0; j < 2; j++) {               // B: 512 16B-chunks
            int idx = j * 256 + tid;
            int r = idx >> 2, c = idx & 3;
            cp16(sbase + ST_B + r * RSTR + c * 16, pB + (size_t)r * KTOT + kbase + c * 8);
        }
    };

    float acc[4][4][4];
    #pragma unroll
    for (int i = 0; i < 4; i++)
        #pragma unroll
        for (int j = 0; j < 4; j++)
            #pragma unroll
            for (int q = 0; q < 4; q++) acc[i][j][q] = 0.f;

    const uint32_t aAddr = (uint32_t)(wm * 64 + (lane & 15)) * RSTR + (lane >> 4) * 16;
    const uint32_t bAddr = (uint32_t)(wn * 32 + ((lane >> 4) & 1) * 8 + (lane & 7)) * RSTR
                           + ((lane >> 3) & 1) * 16;

    const int NK = KTOT / 32;
    load_stage(0, 0);  cp_commit();
    load_stage(1, 32); cp_commit();
    load_stage(2, 64); cp_commit();
    load_stage(3, 96); cp_commit();

    for (int s = 0; s < NK; s++) {
        cp_wait<3>();
        __syncthreads();

        uint32_t sbase = sb + (s % NST) * ST_SZ;
        #pragma unroll
        for (int kk = 0; kk < 2; kk++) {
            uint32_t koff = kk * 32;
            uint32_t ah[4][4], bh[2][4];
            #pragma unroll
            for (int mi = 0; mi < 4; mi++)
                ldm_x4(ah[mi], sbase + ST_A + aAddr + mi * (16 * RSTR) + koff);
            #pragma unroll
            for (int nq = 0; nq < 2; nq++)
                ldm_x4(bh[nq], sbase + ST_B + bAddr + nq * (16 * RSTR) + koff);
            #pragma unroll
            for (int mi = 0; mi < 4; mi++)
                #pragma unroll
                for (int nq = 0; nq < 2; nq++) {
                    mma16816(acc[mi][2 * nq],     ah[mi], bh[nq]);
                    mma16816(acc[mi][2 * nq + 1], ah[mi], bh[nq] + 2);
                }
        }

        if (s + 4 < NK) load_stage((s + 4) % NST, (s + 4) * 32);
        cp_commit();
    }

    // ---------------- epilogue (G1 direct stores; G2 fused combine via v2 reductions) ----------------
    const int colbase = n0 + wn * 32 + (lane & 3) * 2;
    const int rowbase = wm * 64 + (lane >> 2);
    float2 bvv[4];
    #pragma unroll
    for (int ni = 0; ni < 4; ni++)
        bvv[ni] = *(const float2*)(bias + (size_t)e * NF + colbase + ni * 8);
    #pragma unroll
    for (int mi = 0; mi < 4; mi++) {
        #pragma unroll
        for (int half = 0; half < 2; half++) {
            int r = rowbase + mi * 16 + half * 8;
            size_t grow = arow0 + r;
            if (G1) {
                #pragma unroll
                for (int ni = 0; ni < 4; ni++) {
                    int col = colbase + ni * 8;
                    float g0 = gelu_exact(acc[mi][ni][half * 2 + 0] + bvv[ni].x);
                    float g1 = gelu_exact(acc[mi][ni][half * 2 + 1] + bvv[ni].y);
                    *(uint32_t*)(Oh + grow * NF + col) =
                        pack_h2(__float2half_rn(g0), __float2half_rn(g1));
                }
            } else {
                int tok = g_rowidx[grow];
                if (tok >= 0) {
                    float w = g_wn[grow];
                    float* op = Of + (size_t)tok * DMODEL;
                    #pragma unroll
                    for (int ni = 0; ni < 4; ni++) {
                        int col = colbase + ni * 8;
                        float v0 = w * (acc[mi][ni][half * 2 + 0] + bvv[ni].x);
                        float v1 = w * (acc[mi][ni][half * 2 + 1] + bvv[ni].y);
                        red_v2(op + col, v0, v1);
                    }
                }
            }
        }
    }
}

// ---------------- launch ----------------
extern "C" void kernel_launch(void* const* d_in, const int* in_sizes, int n_in,
                              void* d_out, int out_size) {
    const float* x  = (const float*)d_in[0];
    const float* Wr = (const float*)d_in[1];
    const float* br = (const float*)d_in[2];
    const float* W1 = (const float*)d_in[3];
    const float* b1 = (const float*)d_in[4];
    const float* W2 = (const float*)d_in[5];
    const float* b2 = (const float*)d_in[6];
    float* out = (float*)d_out;

    int N = in_sizes[0] / DMODEL;
    if (N > NMAX) N = NMAX;
    int cap = (5 * N + 15) / 16;
    if (cap > CAPMAX) cap = CAPMAX;
    int tpe = (cap + 127) / 128;
    int nblk = (N + 255) / 256;

    void *x16, *hh, *w1h, *w2h, *ridx;
    cudaGetSymbolAddress(&x16, g_X16);
    cudaGetSymbolAddress(&hh,  g_Hh);
    cudaGetSymbolAddress(&w1h, g_W1h); cudaGetSymbolAddress(&w2h, g_W2h);
    cudaGetSymbolAddress(&ridx, g_rowidx);

    cudaFuncSetAttribute(gemm_mma<DMODEL, DFF, true>,
                         cudaFuncAttributeMaxDynamicSharedMemorySize, SMEM_TOT);
    cudaFuncSetAttribute(gemm_mma<DFF, DMODEL, false>,
                         cudaFuncAttributeMaxDynamicSharedMemorySize, SMEM_TOT);

    // side stream for weight conversion (event fork/join: graph-capture safe)
    cudaStream_t s2;
    cudaStreamCreateWithFlags(&s2, cudaStreamNonBlocking);
    cudaEvent_t ev0, ev1;
    cudaEventCreateWithFlags(&ev0, cudaEventDisableTiming);
    cudaEventCreateWithFlags(&ev1, cudaEventDisableTiming);

    cudaMemsetAsync(out, 0, (size_t)out_size * sizeof(float));
    cudaMemsetAsync(ridx, 0xFF, (size_t)EROWS * sizeof(int));   // all slots -> -1
    cudaEventRecord(ev0, 0);
    cudaStreamWaitEvent(s2, ev0, 0);
    wconvert_kernel<<<dim3(DFF / 32, DMODEL / 32, NEXP), 256, 0, s2>>>(
        W1, (__half*)w1h, DMODEL, DFF);
    wconvert_kernel<<<dim3(DMODEL / 32, DFF / 32, NEXP), 256, 0, s2>>>(
        W2, (__half*)w2h, DFF, DMODEL);
    cudaEventRecord(ev1, s2);

    router_kernel<<<(N * 32 + 255) / 256, 256>>>(x, Wr, br, (__half*)x16, N);
    count_kernel<<<nblk, 256>>>(N);
    scan_kernel<<<1, NB>>>(cap);
    scatter_kernel<<<nblk, 256>>>(N, cap);

    cudaStreamWaitEvent(0, ev1, 0);

    dim3 g1(DFF / 128, NEXP * tpe);
    gemm_mma<DMODEL, DFF, true><<<g1, 256, SMEM_TOT>>>(
        (const __half*)x16, (const __half*)w1h, b1,
        (__half*)hh, nullptr, cap, tpe);

    dim3 g2(DMODEL / 128, NEXP * tpe);
    gemm_mma<DFF, DMODEL, false><<<g2, 256, SMEM_TOT>>>(
        (const __half*)hh, (const __half*)w2h, b2,
        nullptr, out, cap, tpe);
}